// round 9
// baseline (speedup 1.0000x reference)
#include <cuda_runtime.h>
#include <cuda_fp16.h>
#include <math.h>
#include <stdint.h>

#define DIM   2048
#define NH    16
#define HD    128
#define SEQ   2048
#define BATCH 2
#define MROWS (BATCH*SEQ)   // 4096
#define WSZ   ((size_t)DIM*DIM)

// ---- scratch (device globals, all fp16) ----
__device__ __half g_Xhi[(size_t)MROWS*DIM];
__device__ __half g_Xlo[(size_t)MROWS*DIM];
__device__ __half g_W[4][WSZ];            // plain fp16, [K,N]
__device__ __half g_Qhi[(size_t)MROWS*DIM];
__device__ __half g_Qlo[(size_t)MROWS*DIM];
__device__ __half g_Kh [(size_t)MROWS*DIM];
__device__ __half g_Vh [(size_t)MROWS*DIM];
__device__ __half g_Ohi[(size_t)MROWS*DIM];
__device__ __half g_Olo[(size_t)MROWS*DIM];

// ---------- PTX helpers ----------
__device__ __forceinline__ void cp16(uint32_t dst, const void* src) {
    asm volatile("cp.async.cg.shared.global [%0], [%1], 16;\n" :: "r"(dst), "l"(src));
}
__device__ __forceinline__ void ldsm4(uint32_t* r, uint32_t a) {
    asm volatile("ldmatrix.sync.aligned.m8n8.x4.shared.b16 {%0,%1,%2,%3}, [%4];\n"
        : "=r"(r[0]), "=r"(r[1]), "=r"(r[2]), "=r"(r[3]) : "r"(a));
}
__device__ __forceinline__ void ldsm4t(uint32_t* r, uint32_t a) {
    asm volatile("ldmatrix.sync.aligned.m8n8.x4.trans.shared.b16 {%0,%1,%2,%3}, [%4];\n"
        : "=r"(r[0]), "=r"(r[1]), "=r"(r[2]), "=r"(r[3]) : "r"(a));
}
__device__ __forceinline__ void mma16816(float* c, const uint32_t* a, const uint32_t* b) {
    asm volatile("mma.sync.aligned.m16n8k16.row.col.f32.f16.f16.f32 "
        "{%0,%1,%2,%3}, {%4,%5,%6,%7}, {%8,%9}, {%0,%1,%2,%3};\n"
        : "+f"(c[0]), "+f"(c[1]), "+f"(c[2]), "+f"(c[3])
        : "r"(a[0]), "r"(a[1]), "r"(a[2]), "r"(a[3]), "r"(b[0]), "r"(b[1]));
}
__device__ __forceinline__ uint32_t packh(float x, float y) {
    __half2 t = __floats2half2_rn(x, y);
    return *(uint32_t*)&t;
}
__device__ __forceinline__ void split2h(float x, float y, uint32_t& hi, uint32_t& lo) {
    float hx = __half2float(__float2half_rn(x));
    float hy = __half2float(__float2half_rn(y));
    hi = packh(hx, hy);
    lo = packh(x - hx, y - hy);
}
__device__ __forceinline__ uint32_t smem_u32(const void* p) {
    return (uint32_t)__cvta_generic_to_shared(p);
}

// ============================================================
// fp32 -> fp16 hi/lo split, 8 elem/thread
// ============================================================
__global__ __launch_bounds__(256) void split_kernel(
    const float* __restrict__ in, __half* __restrict__ hi,
    __half* __restrict__ lo, int n8)
{
    int i = blockIdx.x * 256 + threadIdx.x;
    if (i >= n8) return;
    float4 a = ((const float4*)in)[2*i];
    float4 b = ((const float4*)in)[2*i+1];
    uint4 h, l;
    split2h(a.x, a.y, h.x, l.x);
    split2h(a.z, a.w, h.y, l.y);
    split2h(b.x, b.y, h.z, l.z);
    split2h(b.z, b.w, h.w, l.w);
    ((uint4*)hi)[i] = h;
    ((uint4*)lo)[i] = l;
}

__global__ __launch_bounds__(256) void cvt4_kernel(
    const float* __restrict__ w0, const float* __restrict__ w1,
    const float* __restrict__ w2, const float* __restrict__ w3,
    __half* __restrict__ out, int n8)
{
    int i = blockIdx.x * 256 + threadIdx.x;
    if (i >= n8) return;
    int z = blockIdx.y;
    const float* in = (z == 0) ? w0 : (z == 1) ? w1 : (z == 2) ? w2 : w3;
    __half* o = out + (size_t)z * WSZ;
    float4 a = ((const float4*)in)[2*i];
    float4 b = ((const float4*)in)[2*i+1];
    uint4 r;
    r.x = packh(a.x, a.y); r.y = packh(a.z, a.w);
    r.z = packh(b.x, b.y); r.w = packh(b.z, b.w);
    ((uint4*)o)[i] = r;
}

// ============================================================
// Persistent fp16x2 mma.sync GEMM, 4x2 warp grid (warp tile 32x64)
// to minimize smem fragment re-reads. BK=64, 2-stage ring across
// tiles, 2 CTAs/SM.
// ============================================================
#define GBM 128
#define GBN 128
#define GBK 64
#define APAD 72
#define BPAD 136
#define SAB (GBM*APAD*2)            // 18432
#define SBB (GBK*BPAD*2)            // 17408
#define STAGE (2*SAB + SBB)         // 54272
#define GEMM_SMEM (2*STAGE)         // 108544 -> 2 CTAs/SM
#define CPT 32
#define TPZ (MROWS/GBM * DIM/GBN)   // 512

__global__ __launch_bounds__(256, 2) void gemm_fp16x2(
    const __half* __restrict__ Ah, const __half* __restrict__ Al,
    const __half* __restrict__ B,
    __half* __restrict__ Qh, __half* __restrict__ Ql,
    __half* __restrict__ Kh, __half* __restrict__ Vh,
    float* __restrict__ Cout,
    const float* __restrict__ fcos, const float* __restrict__ fsin,
    int fused, int ntiles)
{
    extern __shared__ char smraw[];
    const uint32_t sb = smem_u32(smraw);

    const int tid  = threadIdx.x;
    const int bid  = blockIdx.x;
    const int G    = gridDim.x;
    const int warp = tid >> 5, lane = tid & 31;
    const int wm = warp >> 1, wn = warp & 1;   // 4x2 grid, warp tile 32x64

    auto issue_chunk = [&](int myc) {
        int t = bid + (myc >> 5) * G;
        if (t >= ntiles) return;
        int z   = t / TPZ;
        int rem = t - z * TPZ;
        int row0 = (rem >> 4) * GBM;
        int col0 = (rem & 15) * GBN;
        const __half* bp = B + (size_t)z * WSZ;
        const uint32_t base = sb + (uint32_t)(myc & 1) * STAGE;
        const int k0 = (myc & (CPT-1)) * GBK;
        for (int idx = tid; idx < 1024; idx += 256) {
            int r = idx >> 3, o = (idx & 7) * 8;
            uint32_t d = base + (uint32_t)(r * APAD + o) * 2;
            size_t g = (size_t)(row0 + r) * DIM + k0 + o;
            cp16(d,       Ah + g);
            cp16(d + SAB, Al + g);
        }
        for (int idx = tid; idx < 1024; idx += 256) {
            int r = idx >> 4, o = (idx & 15) * 8;
            uint32_t d = base + 2*SAB + (uint32_t)(r * BPAD + o) * 2;
            cp16(d, bp + (size_t)(k0 + r) * DIM + col0 + o);
        }
    };

    issue_chunk(0);
    asm volatile("cp.async.commit_group;\n");
    issue_chunk(1);
    asm volatile("cp.async.commit_group;\n");

    const int arow  = (lane & 7) + ((lane >> 3) & 1) * 8;
    const int acol8 = (lane >> 4) * 8;
    const int brow8 = (lane & 7) + ((lane >> 3) & 1) * 8;
    const int bnc8  = (lane >> 4) * 8;
    const float qscale = 0.08838834764831845f;

    int myc = 0;
    for (int t = bid; t < ntiles; t += G) {
        const int z   = t / TPZ;
        const int rem = t - z * TPZ;
        const int row0 = (rem >> 4) * GBM;
        const int col0 = (rem & 15) * GBN;
        const int mode = fused ? z : 3;

        float acc[2][8][4];
#pragma unroll
        for (int i = 0; i < 2; i++)
#pragma unroll
            for (int j = 0; j < 8; j++)
#pragma unroll
                for (int r = 0; r < 4; r++) acc[i][j][r] = 0.f;

        for (int i = 0; i < CPT; i++, myc++) {
            asm volatile("cp.async.wait_group 1;\n");
            __syncthreads();

            const uint32_t base = sb + (uint32_t)(myc & 1) * STAGE;
            const uint32_t bAh = base, bAl = base + SAB;
            const uint32_t bB  = base + 2*SAB;

#pragma unroll
            for (int ks = 0; ks < 4; ks++) {
                const int acol = ks * 16 + acol8;
                const int brow = ks * 16 + brow8;
                // B fragments: 64 cols = 8 n8-frags via 4 ldsm4t
                uint32_t bfr[8][2];
#pragma unroll
                for (int g = 0; g < 4; g++) {
                    int nc = wn * 64 + g * 16 + bnc8;
                    uint32_t t4[4];
                    ldsm4t(t4, bB + (uint32_t)(brow * BPAD + nc) * 2);
                    bfr[g*2][0] = t4[0]; bfr[g*2][1] = t4[1];
                    bfr[g*2+1][0] = t4[2]; bfr[g*2+1][1] = t4[3];
                }
                uint32_t af[2][4];
#pragma unroll
                for (int mt = 0; mt < 2; mt++)
                    ldsm4(af[mt], bAh + (uint32_t)((wm*32 + mt*16 + arow) * APAD + acol) * 2);
#pragma unroll
                for (int mt = 0; mt < 2; mt++)
#pragma unroll
                    for (int nt = 0; nt < 8; nt++)
                        mma16816(acc[mt][nt], af[mt], bfr[nt]);
#pragma unroll
                for (int mt = 0; mt < 2; mt++)
                    ldsm4(af[mt], bAl + (uint32_t)((wm*32 + mt*16 + arow) * APAD + acol) * 2);
#pragma unroll
                for (int mt = 0; mt < 2; mt++)
#pragma unroll
                    for (int nt = 0; nt < 8; nt++)
                        mma16816(acc[mt][nt], af[mt], bfr[nt]);
            }

            __syncthreads();
            issue_chunk(myc + 2);
            asm volatile("cp.async.commit_group;\n");
        }

        // ---- fused epilogue ----
#pragma unroll
        for (int mt = 0; mt < 2; mt++) {
#pragma unroll
            for (int nt = 0; nt < 8; nt++) {
                int r = row0 + wm * 32 + mt * 16 + (lane >> 2);
                int c = col0 + wn * 64 + nt * 8 + (lane & 3) * 2;
                float a0 = acc[mt][nt][0], a1 = acc[mt][nt][1];
                float a2 = acc[mt][nt][2], a3 = acc[mt][nt][3];
                size_t o0 = (size_t)r * DIM + c, o1 = (size_t)(r + 8) * DIM + c;
                if (mode == 3) {
                    *(float2*)(Cout + o0) = make_float2(a0, a1);
                    *(float2*)(Cout + o1) = make_float2(a2, a3);
                } else if (mode == 2) {
                    *(uint32_t*)(Vh + o0) = packh(a0, a1);
                    *(uint32_t*)(Vh + o1) = packh(a2, a3);
                } else {
                    int i2 = (c & (HD - 1)) >> 1;
                    int s0 = r & (SEQ - 1), s1 = (r + 8) & (SEQ - 1);
                    float c0 = fcos[s0 * (HD/2) + i2], n0 = fsin[s0 * (HD/2) + i2];
                    float c1 = fcos[s1 * (HD/2) + i2], n1 = fsin[s1 * (HD/2) + i2];
                    float t0 = a0 * c0 - a1 * n0, t1 = a0 * n0 + a1 * c0;
                    float t2 = a2 * c1 - a3 * n1, t3 = a2 * n1 + a3 * c1;
                    if (mode == 0) {
                        t0 *= qscale; t1 *= qscale; t2 *= qscale; t3 *= qscale;
                        uint32_t h0, l0, h1, l1;
                        split2h(t0, t1, h0, l0);
                        split2h(t2, t3, h1, l1);
                        *(uint32_t*)(Qh + o0) = h0; *(uint32_t*)(Ql + o0) = l0;
                        *(uint32_t*)(Qh + o1) = h1; *(uint32_t*)(Ql + o1) = l1;
                    } else {
                        *(uint32_t*)(Kh + o0) = packh(t0, t1);
                        *(uint32_t*)(Kh + o1) = packh(t2, t3);
                    }
                }
            }
        }
    }
}

// ============================================================
// fp16x2 causal flash attention, 64x64 tiles, 3 CTAs/SM.
// ============================================================
#define AQ  64
#define APD 136
#define TILE_E (AQ*APD)
#define ATTN_SMEM (4*TILE_E*2)     // 69632

__global__ __launch_bounds__(128, 3) void attn_tc_kernel(
    const __half* __restrict__ Qhi, const __half* __restrict__ Qlo,
    const __half* __restrict__ Kg,  const __half* __restrict__ Vg,
    __half* __restrict__ Ohi, __half* __restrict__ Olo)
{
    extern __shared__ __half sm[];
    __half* sQh = sm;
    __half* sQl = sQh + TILE_E;
    __half* sK  = sQl + TILE_E;
    __half* sV  = sK  + TILE_E;
    const uint32_t uQh = smem_u32(sQh);
    const uint32_t uQl = smem_u32(sQl);
    const uint32_t uK  = smem_u32(sK);
    const uint32_t uV  = smem_u32(sV);

    const int tid = threadIdx.x, warp = tid >> 5, lane = tid & 31;
    const int qt = (int)(gridDim.x - 1 - blockIdx.x);
    const int h = blockIdx.y, b = blockIdx.z;
    const int q0 = qt * AQ;
    const size_t rowbase = (size_t)b * SEQ;
    const size_t colh = (size_t)h * HD;

#define LOADTILE(dstu, src, r0) do {                                           \
    for (int c0_ = tid; c0_ < 1024; c0_ += 128) {                              \
        int r_ = c0_ >> 4, o_ = (c0_ & 15) * 8;                                \
        cp16((dstu) + (r_*APD + o_)*2,                                         \
             (src) + (rowbase + (r0) + r_)*DIM + colh + o_);                   \
    } } while (0)

    LOADTILE(uQh, Qhi, q0);
    LOADTILE(uQl, Qlo, q0);
    LOADTILE(uK,  Kg,  0);
    asm volatile("cp.async.commit_group;\n");

    float o[16][4];
#pragma unroll
    for (int nt = 0; nt < 16; nt++)
#pragma unroll
        for (int r = 0; r < 4; r++) o[nt][r] = 0.f;
    float m0 = -INFINITY, m1 = -INFINITY, l0 = 0.f, l1 = 0.f;

    const int nkv = qt + 1;
    const int arow = (lane & 7) + ((lane >> 3) & 1) * 8;
    const int acol8 = (lane >> 4) * 8;
    const int bro8 = (lane & 7) + ((lane >> 4) << 3);
    const int bco8 = ((lane >> 3) & 1) * 8;
    const int vro8 = (lane & 7) + ((lane >> 3) & 1) * 8;
    const int vco8 = (lane >> 4) * 8;

    for (int kt = 0; kt < nkv; kt++) {
        asm volatile("cp.async.wait_group 0;\n");
        __syncthreads();

        LOADTILE(uV, Vg, kt*AQ);
        asm volatile("cp.async.commit_group;\n");

        float s[8][4];
#pragma unroll
        for (int t = 0; t < 8; t++)
#pragma unroll
            for (int r = 0; r < 4; r++) s[t][r] = 0.f;

#pragma unroll
        for (int ks = 0; ks < 8; ks++) {
            uint32_t qh4[4], ql4[4];
            uint32_t aoff = ((warp*16 + arow)*APD + ks*16 + acol8)*2;
            ldsm4(qh4, uQh + aoff);
            ldsm4(ql4, uQl + aoff);
#pragma unroll
            for (int bt = 0; bt < 4; bt++) {
                uint32_t kh4[4];
                uint32_t boff = ((bt*16 + bro8)*APD + ks*16 + bco8)*2;
                ldsm4(kh4, uK + boff);
                mma16816(s[2*bt],   qh4, kh4);
                mma16816(s[2*bt],   ql4, kh4);
                mma16816(s[2*bt+1], qh4, kh4+2);
                mma16816(s[2*bt+1], ql4, kh4+2);
            }
        }

        if (kt == qt) {
            int rl0 = warp*16 + (lane >> 2);
            int cb = (lane & 3) * 2;
#pragma unroll
            for (int t = 0; t < 8; t++) {
                int c0 = t*8 + cb, c1 = c0 + 1;
                if (c0 > rl0)     s[t][0] = -INFINITY;
                if (c1 > rl0)     s[t][1] = -INFINITY;
                if (c0 > rl0 + 8) s[t][2] = -INFINITY;
                if (c1 > rl0 + 8) s[t][3] = -INFINITY;
            }
        }

        float mt0 = -INFINITY, mt1 = -INFINITY;
#pragma unroll
        for (int t = 0; t < 8; t++) {
            mt0 = fmaxf(mt0, fmaxf(s[t][0], s[t][1]));
            mt1 = fmaxf(mt1, fmaxf(s[t][2], s[t][3]));
        }
        mt0 = fmaxf(mt0, __shfl_xor_sync(0xffffffffu, mt0, 1));
        mt0 = fmaxf(mt0, __shfl_xor_sync(0xffffffffu, mt0, 2));
        mt1 = fmaxf(mt1, __shfl_xor_sync(0xffffffffu, mt1, 1));
        mt1 = fmaxf(mt1, __shfl_xor_sync(0xffffffffu, mt1, 2));
        float mn0 = fmaxf(m0, mt0), mn1 = fmaxf(m1, mt1);
        float corr0 = __expf(m0 - mn0), corr1 = __expf(m1 - mn1);
        m0 = mn0; m1 = mn1;

        float p[8][4];
        float sum0 = 0.f, sum1 = 0.f;
#pragma unroll
        for (int t = 0; t < 8; t++) {
            p[t][0] = __expf(s[t][0] - mn0);
            p[t][1] = __expf(s[t][1] - mn0);
            p[t][2] = __expf(s[t][2] - mn1);
            p[t][3] = __expf(s[t][3] - mn1);
            sum0 += p[t][0] + p[t][1];
            sum1 += p[t][2] + p[t][3];
        }
        sum0 += __shfl_xor_sync(0xffffffffu, sum0, 1);
        sum0 += __shfl_xor_sync(0xffffffffu, sum0, 2);
        sum1 += __shfl_xor_sync(0xffffffffu, sum1, 1);
        sum1 += __shfl_xor_sync(0xffffffffu, sum1, 2);
        l0 = l0 * corr0 + sum0;
        l1 = l1 * corr1 + sum1;

        uint32_t ph[4][4], pl[4][4];
#pragma unroll
        for (int c = 0; c < 4; c++) {
            split2h(p[2*c][0],   p[2*c][1],   ph[c][0], pl[c][0]);
            split2h(p[2*c][2],   p[2*c][3],   ph[c][1], pl[c][1]);
            split2h(p[2*c+1][0], p[2*c+1][1], ph[c][2], pl[c][2]);
            split2h(p[2*c+1][2], p[2*c+1][3], ph[c][3], pl[c][3]);
        }

#pragma unroll
        for (int nt = 0; nt < 16; nt++) {
            o[nt][0] *= corr0; o[nt][1] *= corr0;
            o[nt][2] *= corr1; o[nt][3] *= corr1;
        }

        asm volatile("cp.async.wait_group 0;\n");
        __syncthreads();

        if (kt + 1 < nkv) {
            LOADTILE(uK, Kg, (kt+1)*AQ);
        }
        asm volatile("cp.async.commit_group;\n");

#pragma unroll
        for (int c = 0; c < 4; c++) {
#pragma unroll
            for (int np = 0; np < 8; np++) {
                uint32_t vh4[4];
                uint32_t voff = ((c*16 + vro8)*APD + np*16 + vco8)*2;
                ldsm4t(vh4, uV + voff);
                mma16816(o[2*np],   ph[c], vh4);
                mma16816(o[2*np],   pl[c], vh4);
                mma16816(o[2*np+1], ph[c], vh4+2);
                mma16816(o[2*np+1], pl[c], vh4+2);
            }
        }
    }

    float inv0 = 1.f / l0, inv1 = 1.f / l1;
    size_t r0g = rowbase + q0 + warp*16 + (lane >> 2);
    size_t cg  = colh + (lane & 3)*2;
#pragma unroll
    for (int nt = 0; nt < 16; nt++) {
        uint32_t hi0, lo0, hi1, lo1;
        split2h(o[nt][0]*inv0, o[nt][1]*inv0, hi0, lo0);
        split2h(o[nt][2]*inv1, o[nt][3]*inv1, hi1, lo1);
        size_t off0 = r0g*DIM + cg + nt*8;
        size_t off1 = (r0g+8)*DIM + cg + nt*8;
        *(uint32_t*)(Ohi + off0) = hi0;
        *(uint32_t*)(Olo + off0) = lo0;
        *(uint32_t*)(Ohi + off1) = hi1;
        *(uint32_t*)(Olo + off1) = lo1;
    }
}

// ============================================================
extern "C" void kernel_launch(void* const* d_in, const int* in_sizes, int n_in,
                              void* d_out, int out_size)
{
    const float* x   = (const float*)d_in[0];
    const float* wq  = (const float*)d_in[1];
    const float* wk  = (const float*)d_in[2];
    const float* wv  = (const float*)d_in[3];
    const float* wo  = (const float*)d_in[4];
    const float* fco = (const float*)d_in[5];
    const float* fsi = (const float*)d_in[6];
    float* out = (float*)d_out;

    __half *Xhi, *Xlo, *W, *Qhi, *Qlo, *Kh, *Vh, *Ohi, *Olo;
    cudaGetSymbolAddress((void**)&Xhi, g_Xhi);
    cudaGetSymbolAddress((void**)&Xlo, g_Xlo);
    cudaGetSymbolAddress((void**)&W,   g_W);
    cudaGetSymbolAddress((void**)&Qhi, g_Qhi);
    cudaGetSymbolAddress((void**)&Qlo, g_Qlo);
    cudaGetSymbolAddress((void**)&Kh,  g_Kh);
    cudaGetSymbolAddress((void**)&Vh,  g_Vh);
    cudaGetSymbolAddress((void**)&Ohi, g_Ohi);
    cudaGetSymbolAddress((void**)&Olo, g_Olo);

    cudaFuncSetAttribute(gemm_fp16x2,
        cudaFuncAttributeMaxDynamicSharedMemorySize, GEMM_SMEM);
    cudaFuncSetAttribute(attn_tc_kernel,
        cudaFuncAttributeMaxDynamicSharedMemorySize, ATTN_SMEM);

    const int nX8 = MROWS * DIM / 8;
    const int nW8 = DIM * DIM / 8;

    split_kernel<<<(nX8 + 255)/256, 256>>>(x, Xhi, Xlo, nX8);
    dim3 cgrid((nW8 + 255)/256, 4);
    cvt4_kernel<<<cgrid, 256>>>(wq, wk, wv, wo, W, nW8);

    gemm_fp16x2<<<296, 256, GEMM_SMEM>>>(
        Xhi, Xlo, W,
        Qhi, Qlo, Kh, Vh,
        nullptr, fco, fsi, 1, 3*TPZ);

    dim3 agrid(SEQ / AQ, NH, BATCH);       // (32, 16, 2)
    attn_tc_kernel<<<agrid, 128, ATTN_SMEM>>>(Qhi, Qlo, Kh, Vh, Ohi, Olo);

    gemm_fp16x2<<<296, 256, GEMM_SMEM>>>(
        Ohi, Olo, W + 3*WSZ,
        nullptr, nullptr, nullptr, nullptr,
        out, fco, fsi, 0, TPZ);
}

// round 11
// speedup vs baseline: 1.5148x; 1.5148x over previous
#include <cuda_runtime.h>
#include <cuda_fp16.h>
#include <math.h>
#include <stdint.h>

#define DIM   2048
#define NH    16
#define HD    128
#define SEQ   2048
#define BATCH 2
#define MROWS (BATCH*SEQ)   // 4096
#define WSZ   ((size_t)DIM*DIM)

// ---- scratch (device globals, all fp16) ----
__device__ __half g_X [(size_t)MROWS*DIM];
__device__ __half g_W[4][WSZ];            // plain fp16, [K,N]
__device__ __half g_Qhi[(size_t)MROWS*DIM];
__device__ __half g_Qlo[(size_t)MROWS*DIM];
__device__ __half g_Kh [(size_t)MROWS*DIM];
__device__ __half g_Vh [(size_t)MROWS*DIM];
__device__ __half g_Oh [(size_t)MROWS*DIM];

// ---------- PTX helpers ----------
__device__ __forceinline__ void cp16(uint32_t dst, const void* src) {
    asm volatile("cp.async.cg.shared.global [%0], [%1], 16;\n" :: "r"(dst), "l"(src));
}
__device__ __forceinline__ void ldsm4(uint32_t* r, uint32_t a) {
    asm volatile("ldmatrix.sync.aligned.m8n8.x4.shared.b16 {%0,%1,%2,%3}, [%4];\n"
        : "=r"(r[0]), "=r"(r[1]), "=r"(r[2]), "=r"(r[3]) : "r"(a));
}
__device__ __forceinline__ void ldsm4t(uint32_t* r, uint32_t a) {
    asm volatile("ldmatrix.sync.aligned.m8n8.x4.trans.shared.b16 {%0,%1,%2,%3}, [%4];\n"
        : "=r"(r[0]), "=r"(r[1]), "=r"(r[2]), "=r"(r[3]) : "r"(a));
}
__device__ __forceinline__ void mma16816(float* c, const uint32_t* a, const uint32_t* b) {
    asm volatile("mma.sync.aligned.m16n8k16.row.col.f32.f16.f16.f32 "
        "{%0,%1,%2,%3}, {%4,%5,%6,%7}, {%8,%9}, {%0,%1,%2,%3};\n"
        : "+f"(c[0]), "+f"(c[1]), "+f"(c[2]), "+f"(c[3])
        : "r"(a[0]), "r"(a[1]), "r"(a[2]), "r"(a[3]), "r"(b[0]), "r"(b[1]));
}
__device__ __forceinline__ uint32_t packh(float x, float y) {
    __half2 t = __floats2half2_rn(x, y);
    return *(uint32_t*)&t;
}
__device__ __forceinline__ void split2h(float x, float y, uint32_t& hi, uint32_t& lo) {
    float hx = __half2float(__float2half_rn(x));
    float hy = __half2float(__float2half_rn(y));
    hi = packh(hx, hy);
    lo = packh(x - hx, y - hy);
}
__device__ __forceinline__ uint32_t smem_u32(const void* p) {
    return (uint32_t)__cvta_generic_to_shared(p);
}

// ============================================================
// fp32 -> fp16 convert, 8 elem/thread.
// z=0: X (n8x chunks). z=1..4: weights (n8w chunks each).
// ============================================================
__global__ __launch_bounds__(256) void cvt5_kernel(
    const float* __restrict__ x,
    const float* __restrict__ w0, const float* __restrict__ w1,
    const float* __restrict__ w2, const float* __restrict__ w3,
    __half* __restrict__ xo, __half* __restrict__ wo_,
    int n8x, int n8w)
{
    int i = blockIdx.x * 256 + threadIdx.x;
    int z = blockIdx.y;
    int lim = (z == 0) ? n8x : n8w;
    if (i >= lim) return;
    const float* in = (z == 0) ? x : (z == 1) ? w0 : (z == 2) ? w1 : (z == 3) ? w2 : w3;
    __half* o = (z == 0) ? xo : (wo_ + (size_t)(z-1) * WSZ);
    float4 a = ((const float4*)in)[2*i];
    float4 b = ((const float4*)in)[2*i+1];
    uint4 r;
    r.x = packh(a.x, a.y); r.y = packh(a.z, a.w);
    r.z = packh(b.x, b.y); r.w = packh(b.z, b.w);
    ((uint4*)o)[i] = r;
}

// ============================================================
// Persistent plain-fp16 mma.sync GEMM: C = A @ B, BK=64,
// 2-stage cp.async ring across tiles, 2x4 warp grid, 2 CTAs/SM.
// fused: z=0 rope+scale+split Q, z=1 rope K, z=2 V; else fp32 out
// ============================================================
#define GBM 128
#define GBN 128
#define GBK 64
#define APAD 72
#define BPAD 136
#define SAB (GBM*APAD*2)            // 18432
#define SBB (GBK*BPAD*2)            // 17408
#define STAGE (SAB + SBB)           // 35840
#define GEMM_SMEM (2*STAGE)         // 71680 -> 2 CTAs/SM
#define CPT 32
#define TPZ (MROWS/GBM * DIM/GBN)   // 512

__global__ __launch_bounds__(256, 2) void gemm_fp16(
    const __half* __restrict__ A,
    const __half* __restrict__ B,
    __half* __restrict__ Qh, __half* __restrict__ Ql,
    __half* __restrict__ Kh, __half* __restrict__ Vh,
    float* __restrict__ Cout,
    const float* __restrict__ fcos, const float* __restrict__ fsin,
    int fused, int ntiles)
{
    extern __shared__ char smraw[];
    const uint32_t sb = smem_u32(smraw);

    const int tid  = threadIdx.x;
    const int bid  = blockIdx.x;
    const int G    = gridDim.x;
    const int warp = tid >> 5, lane = tid & 31;
    const int wm = warp >> 2, wn = warp & 3;   // 2x4 grid, warp tile 64x32

    auto issue_chunk = [&](int myc) {
        int t = bid + (myc >> 5) * G;
        if (t >= ntiles) return;
        int z   = t / TPZ;
        int rem = t - z * TPZ;
        int row0 = (rem >> 4) * GBM;
        int col0 = (rem & 15) * GBN;
        const __half* bp = B + (size_t)z * WSZ;
        const uint32_t base = sb + (uint32_t)(myc & 1) * STAGE;
        const int k0 = (myc & (CPT-1)) * GBK;
        for (int idx = tid; idx < 1024; idx += 256) {
            int r = idx >> 3, o = (idx & 7) * 8;
            cp16(base + (uint32_t)(r * APAD + o) * 2,
                 A + (size_t)(row0 + r) * DIM + k0 + o);
        }
        for (int idx = tid; idx < 1024; idx += 256) {
            int r = idx >> 4, o = (idx & 15) * 8;
            cp16(base + SAB + (uint32_t)(r * BPAD + o) * 2,
                 bp + (size_t)(k0 + r) * DIM + col0 + o);
        }
    };

    issue_chunk(0);
    asm volatile("cp.async.commit_group;\n");
    issue_chunk(1);
    asm volatile("cp.async.commit_group;\n");

    const int arow  = (lane & 7) + ((lane >> 3) & 1) * 8;
    const int acol8 = (lane >> 4) * 8;
    const int brow8 = (lane & 7) + ((lane >> 3) & 1) * 8;
    const int bnc8  = (lane >> 4) * 8;
    const float qscale = 0.08838834764831845f;

    int myc = 0;
    for (int t = bid; t < ntiles; t += G) {
        const int z   = t / TPZ;
        const int rem = t - z * TPZ;
        const int row0 = (rem >> 4) * GBM;
        const int col0 = (rem & 15) * GBN;
        const int mode = fused ? z : 3;

        float acc[4][4][4];
#pragma unroll
        for (int i = 0; i < 4; i++)
#pragma unroll
            for (int j = 0; j < 4; j++)
#pragma unroll
                for (int r = 0; r < 4; r++) acc[i][j][r] = 0.f;

        for (int i = 0; i < CPT; i++, myc++) {
            asm volatile("cp.async.wait_group 1;\n");
            __syncthreads();

            const uint32_t base = sb + (uint32_t)(myc & 1) * STAGE;
            const uint32_t bA = base, bB = base + SAB;

#pragma unroll
            for (int ks = 0; ks < 4; ks++) {
                const int acol = ks * 16 + acol8;
                const int brow = ks * 16 + brow8;
                uint32_t bfr[4][2];
#pragma unroll
                for (int hh = 0; hh < 2; hh++) {
                    int nc = wn * 32 + hh * 16 + bnc8;
                    uint32_t t4[4];
                    ldsm4t(t4, bB + (uint32_t)(brow * BPAD + nc) * 2);
                    bfr[hh*2][0] = t4[0]; bfr[hh*2][1] = t4[1];
                    bfr[hh*2+1][0] = t4[2]; bfr[hh*2+1][1] = t4[3];
                }
                uint32_t af[4][4];
#pragma unroll
                for (int mt = 0; mt < 4; mt++)
                    ldsm4(af[mt], bA + (uint32_t)((wm*64 + mt*16 + arow) * APAD + acol) * 2);
#pragma unroll
                for (int mt = 0; mt < 4; mt++)
#pragma unroll
                    for (int nt = 0; nt < 4; nt++)
                        mma16816(acc[mt][nt], af[mt], bfr[nt]);
            }

            __syncthreads();
            issue_chunk(myc + 2);
            asm volatile("cp.async.commit_group;\n");
        }

        // ---- fused epilogue ----
#pragma unroll
        for (int mt = 0; mt < 4; mt++) {
#pragma unroll
            for (int nt = 0; nt < 4; nt++) {
                int r = row0 + wm * 64 + mt * 16 + (lane >> 2);
                int c = col0 + wn * 32 + nt * 8 + (lane & 3) * 2;
                float a0 = acc[mt][nt][0], a1 = acc[mt][nt][1];
                float a2 = acc[mt][nt][2], a3 = acc[mt][nt][3];
                size_t o0 = (size_t)r * DIM + c, o1 = (size_t)(r + 8) * DIM + c;
                if (mode == 3) {
                    *(float2*)(Cout + o0) = make_float2(a0, a1);
                    *(float2*)(Cout + o1) = make_float2(a2, a3);
                } else if (mode == 2) {
                    *(uint32_t*)(Vh + o0) = packh(a0, a1);
                    *(uint32_t*)(Vh + o1) = packh(a2, a3);
                } else {
                    int i2 = (c & (HD - 1)) >> 1;
                    int s0 = r & (SEQ - 1), s1 = (r + 8) & (SEQ - 1);
                    float c0 = fcos[s0 * (HD/2) + i2], n0 = fsin[s0 * (HD/2) + i2];
                    float c1 = fcos[s1 * (HD/2) + i2], n1 = fsin[s1 * (HD/2) + i2];
                    float t0 = a0 * c0 - a1 * n0, t1 = a0 * n0 + a1 * c0;
                    float t2 = a2 * c1 - a3 * n1, t3 = a2 * n1 + a3 * c1;
                    if (mode == 0) {
                        t0 *= qscale; t1 *= qscale; t2 *= qscale; t3 *= qscale;
                        uint32_t h0, l0, h1, l1;
                        split2h(t0, t1, h0, l0);
                        split2h(t2, t3, h1, l1);
                        *(uint32_t*)(Qh + o0) = h0; *(uint32_t*)(Ql + o0) = l0;
                        *(uint32_t*)(Qh + o1) = h1; *(uint32_t*)(Ql + o1) = l1;
                    } else {
                        *(uint32_t*)(Kh + o0) = packh(t0, t1);
                        *(uint32_t*)(Kh + o1) = packh(t2, t3);
                    }
                }
            }
        }
    }
}

// ============================================================
// fp16x2 causal flash attention, 64x64 tiles, 3 CTAs/SM.
// Q split hi/lo; K, V plain. P split. Output plain fp16.
// ============================================================
#define AQ  64
#define APD 136
#define TILE_E (AQ*APD)
#define ATTN_SMEM (4*TILE_E*2)     // 69632

__global__ __launch_bounds__(128, 3) void attn_tc_kernel(
    const __half* __restrict__ Qhi, const __half* __restrict__ Qlo,
    const __half* __restrict__ Kg,  const __half* __restrict__ Vg,
    __half* __restrict__ Og)
{
    extern __shared__ __half sm[];
    __half* sQh = sm;
    __half* sQl = sQh + TILE_E;
    __half* sK  = sQl + TILE_E;
    __half* sV  = sK  + TILE_E;
    const uint32_t uQh = smem_u32(sQh);
    const uint32_t uQl = smem_u32(sQl);
    const uint32_t uK  = smem_u32(sK);
    const uint32_t uV  = smem_u32(sV);

    const int tid = threadIdx.x, warp = tid >> 5, lane = tid & 31;
    const int qt = (int)(gridDim.x - 1 - blockIdx.x);
    const int h = blockIdx.y, b = blockIdx.z;
    const int q0 = qt * AQ;
    const size_t rowbase = (size_t)b * SEQ;
    const size_t colh = (size_t)h * HD;

#define LOADTILE(dstu, src, r0) do {                                           \
    for (int c0_ = tid; c0_ < 1024; c0_ += 128) {                              \
        int r_ = c0_ >> 4, o_ = (c0_ & 15) * 8;                                \
        cp16((dstu) + (r_*APD + o_)*2,                                         \
             (src) + (rowbase + (r0) + r_)*DIM + colh + o_);                   \
    } } while (0)

    LOADTILE(uQh, Qhi, q0);
    LOADTILE(uQl, Qlo, q0);
    LOADTILE(uK,  Kg,  0);
    asm volatile("cp.async.commit_group;\n");

    float o[16][4];
#pragma unroll
    for (int nt = 0; nt < 16; nt++)
#pragma unroll
        for (int r = 0; r < 4; r++) o[nt][r] = 0.f;
    float m0 = -INFINITY, m1 = -INFINITY, l0 = 0.f, l1 = 0.f;

    const int nkv = qt + 1;
    const int arow = (lane & 7) + ((lane >> 3) & 1) * 8;
    const int acol8 = (lane >> 4) * 8;
    const int bro8 = (lane & 7) + ((lane >> 4) << 3);
    const int bco8 = ((lane >> 3) & 1) * 8;
    const int vro8 = (lane & 7) + ((lane >> 3) & 1) * 8;
    const int vco8 = (lane >> 4) * 8;

    for (int kt = 0; kt < nkv; kt++) {
        asm volatile("cp.async.wait_group 0;\n");
        __syncthreads();

        LOADTILE(uV, Vg, kt*AQ);
        asm volatile("cp.async.commit_group;\n");

        float s[8][4];
#pragma unroll
        for (int t = 0; t < 8; t++)
#pragma unroll
            for (int r = 0; r < 4; r++) s[t][r] = 0.f;

#pragma unroll
        for (int ks = 0; ks < 8; ks++) {
            uint32_t qh4[4], ql4[4];
            uint32_t aoff = ((warp*16 + arow)*APD + ks*16 + acol8)*2;
            ldsm4(qh4, uQh + aoff);
            ldsm4(ql4, uQl + aoff);
#pragma unroll
            for (int bt = 0; bt < 4; bt++) {
                uint32_t kh4[4];
                uint32_t boff = ((bt*16 + bro8)*APD + ks*16 + bco8)*2;
                ldsm4(kh4, uK + boff);
                mma16816(s[2*bt],   qh4, kh4);
                mma16816(s[2*bt],   ql4, kh4);
                mma16816(s[2*bt+1], qh4, kh4+2);
                mma16816(s[2*bt+1], ql4, kh4+2);
            }
        }

        if (kt == qt) {
            int rl0 = warp*16 + (lane >> 2);
            int cb = (lane & 3) * 2;
#pragma unroll
            for (int t = 0; t < 8; t++) {
                int c0 = t*8 + cb, c1 = c0 + 1;
                if (c0 > rl0)     s[t][0] = -INFINITY;
                if (c1 > rl0)     s[t][1] = -INFINITY;
                if (c0 > rl0 + 8) s[t][2] = -INFINITY;
                if (c1 > rl0 + 8) s[t][3] = -INFINITY;
            }
        }

        float mt0 = -INFINITY, mt1 = -INFINITY;
#pragma unroll
        for (int t = 0; t < 8; t++) {
            mt0 = fmaxf(mt0, fmaxf(s[t][0], s[t][1]));
            mt1 = fmaxf(mt1, fmaxf(s[t][2], s[t][3]));
        }
        mt0 = fmaxf(mt0, __shfl_xor_sync(0xffffffffu, mt0, 1));
        mt0 = fmaxf(mt0, __shfl_xor_sync(0xffffffffu, mt0, 2));
        mt1 = fmaxf(mt1, __shfl_xor_sync(0xffffffffu, mt1, 1));
        mt1 = fmaxf(mt1, __shfl_xor_sync(0xffffffffu, mt1, 2));
        float mn0 = fmaxf(m0, mt0), mn1 = fmaxf(m1, mt1);
        float corr0 = __expf(m0 - mn0), corr1 = __expf(m1 - mn1);
        m0 = mn0; m1 = mn1;

        float p[8][4];
        float sum0 = 0.f, sum1 = 0.f;
#pragma unroll
        for (int t = 0; t < 8; t++) {
            p[t][0] = __expf(s[t][0] - mn0);
            p[t][1] = __expf(s[t][1] - mn0);
            p[t][2] = __expf(s[t][2] - mn1);
            p[t][3] = __expf(s[t][3] - mn1);
            sum0 += p[t][0] + p[t][1];
            sum1 += p[t][2] + p[t][3];
        }
        sum0 += __shfl_xor_sync(0xffffffffu, sum0, 1);
        sum0 += __shfl_xor_sync(0xffffffffu, sum0, 2);
        sum1 += __shfl_xor_sync(0xffffffffu, sum1, 1);
        sum1 += __shfl_xor_sync(0xffffffffu, sum1, 2);
        l0 = l0 * corr0 + sum0;
        l1 = l1 * corr1 + sum1;

        uint32_t ph[4][4], pl[4][4];
#pragma unroll
        for (int c = 0; c < 4; c++) {
            split2h(p[2*c][0],   p[2*c][1],   ph[c][0], pl[c][0]);
            split2h(p[2*c][2],   p[2*c][3],   ph[c][1], pl[c][1]);
            split2h(p[2*c+1][0], p[2*c+1][1], ph[c][2], pl[c][2]);
            split2h(p[2*c+1][2], p[2*c+1][3], ph[c][3], pl[c][3]);
        }

#pragma unroll
        for (int nt = 0; nt < 16; nt++) {
            o[nt][0] *= corr0; o[nt][1] *= corr0;
            o[nt][2] *= corr1; o[nt][3] *= corr1;
        }

        asm volatile("cp.async.wait_group 0;\n");
        __syncthreads();

        if (kt + 1 < nkv) {
            LOADTILE(uK, Kg, (kt+1)*AQ);
        }
        asm volatile("cp.async.commit_group;\n");

#pragma unroll
        for (int c = 0; c < 4; c++) {
#pragma unroll
            for (int np = 0; np < 8; np++) {
                uint32_t vh4[4];
                uint32_t voff = ((c*16 + vro8)*APD + np*16 + vco8)*2;
                ldsm4t(vh4, uV + voff);
                mma16816(o[2*np],   ph[c], vh4);
                mma16816(o[2*np],   pl[c], vh4);
                mma16816(o[2*np+1], ph[c], vh4+2);
                mma16816(o[2*np+1], pl[c], vh4+2);
            }
        }
    }

    float inv0 = 1.f / l0, inv1 = 1.f / l1;
    size_t r0g = rowbase + q0 + warp*16 + (lane >> 2);
    size_t cg  = colh + (lane & 3)*2;
#pragma unroll
    for (int nt = 0; nt < 16; nt++) {
        size_t off0 = r0g*DIM + cg + nt*8;
        size_t off1 = (r0g+8)*DIM + cg + nt*8;
        *(uint32_t*)(Og + off0) = packh(o[nt][0]*inv0, o[nt][1]*inv0);
        *(uint32_t*)(Og + off1) = packh(o[nt][2]*inv1, o[nt][3]*inv1);
    }
}

// ============================================================
extern "C" void kernel_launch(void* const* d_in, const int* in_sizes, int n_in,
                              void* d_out, int out_size)
{
    const float* x   = (const float*)d_in[0];
    const float* wq  = (const float*)d_in[1];
    const float* wk  = (const float*)d_in[2];
    const float* wv  = (const float*)d_in[3];
    const float* wo  = (const float*)d_in[4];
    const float* fco = (const float*)d_in[5];
    const float* fsi = (const float*)d_in[6];
    float* out = (float*)d_out;

    __half *X, *W, *Qhi, *Qlo, *Kh, *Vh, *Oh;
    cudaGetSymbolAddress((void**)&X,   g_X);
    cudaGetSymbolAddress((void**)&W,   g_W);
    cudaGetSymbolAddress((void**)&Qhi, g_Qhi);
    cudaGetSymbolAddress((void**)&Qlo, g_Qlo);
    cudaGetSymbolAddress((void**)&Kh,  g_Kh);
    cudaGetSymbolAddress((void**)&Vh,  g_Vh);
    cudaGetSymbolAddress((void**)&Oh,  g_Oh);

    cudaFuncSetAttribute(gemm_fp16,
        cudaFuncAttributeMaxDynamicSharedMemorySize, GEMM_SMEM);
    cudaFuncSetAttribute(attn_tc_kernel,
        cudaFuncAttributeMaxDynamicSharedMemorySize, ATTN_SMEM);

    const int n8x = MROWS * DIM / 8;    // 1,048,576  (X: 8M elems)
    const int n8w = DIM * DIM / 8;      //   524,288  (each W: 4M elems)

    dim3 cgrid((n8x + 255)/256, 5);     // grid.x sized for the LARGER tensor
    cvt5_kernel<<<cgrid, 256>>>(x, wq, wk, wv, wo, X, W, n8x, n8w);

    // persistent fused QKV projection (single-pass fp16)
    gemm_fp16<<<296, 256, GEMM_SMEM>>>(
        X, W, Qhi, Qlo, Kh, Vh,
        nullptr, fco, fsi, 1, 3*TPZ);

    dim3 agrid(SEQ / AQ, NH, BATCH);       // (32, 16, 2)
    attn_tc_kernel<<<agrid, 128, ATTN_SMEM>>>(Qhi, Qlo, Kh, Vh, Oh);

    // persistent output projection (single-pass fp16, fp32 store)
    gemm_fp16<<<296, 256, GEMM_SMEM>>>(
        Oh, W + 3*WSZ, nullptr, nullptr, nullptr, nullptr,
        out, fco, fsi, 0, TPZ);
}

// round 12
// speedup vs baseline: 1.7240x; 1.1381x over previous
#include <cuda_runtime.h>
#include <cuda_fp16.h>
#include <math.h>
#include <stdint.h>

#define DIM   2048
#define NH    16
#define HD    128
#define SEQ   2048
#define BATCH 2
#define MROWS (BATCH*SEQ)   // 4096
#define WSZ   ((size_t)DIM*DIM)

// ---- scratch (device globals, all fp16) ----
__device__ __half g_X [(size_t)MROWS*DIM];
__device__ __half g_W[4][WSZ];            // plain fp16, [K,N]
__device__ __half g_Qh [(size_t)MROWS*DIM];
__device__ __half g_Kh [(size_t)MROWS*DIM];
__device__ __half g_Vh [(size_t)MROWS*DIM];
__device__ __half g_Oh [(size_t)MROWS*DIM];

// ---------- PTX helpers ----------
__device__ __forceinline__ void cp16(uint32_t dst, const void* src) {
    asm volatile("cp.async.cg.shared.global [%0], [%1], 16;\n" :: "r"(dst), "l"(src));
}
__device__ __forceinline__ void ldsm4(uint32_t* r, uint32_t a) {
    asm volatile("ldmatrix.sync.aligned.m8n8.x4.shared.b16 {%0,%1,%2,%3}, [%4];\n"
        : "=r"(r[0]), "=r"(r[1]), "=r"(r[2]), "=r"(r[3]) : "r"(a));
}
__device__ __forceinline__ void ldsm4t(uint32_t* r, uint32_t a) {
    asm volatile("ldmatrix.sync.aligned.m8n8.x4.trans.shared.b16 {%0,%1,%2,%3}, [%4];\n"
        : "=r"(r[0]), "=r"(r[1]), "=r"(r[2]), "=r"(r[3]) : "r"(a));
}
__device__ __forceinline__ void mma16816(float* c, const uint32_t* a, const uint32_t* b) {
    asm volatile("mma.sync.aligned.m16n8k16.row.col.f32.f16.f16.f32 "
        "{%0,%1,%2,%3}, {%4,%5,%6,%7}, {%8,%9}, {%0,%1,%2,%3};\n"
        : "+f"(c[0]), "+f"(c[1]), "+f"(c[2]), "+f"(c[3])
        : "r"(a[0]), "r"(a[1]), "r"(a[2]), "r"(a[3]), "r"(b[0]), "r"(b[1]));
}
__device__ __forceinline__ uint32_t packh(float x, float y) {
    __half2 t = __floats2half2_rn(x, y);
    return *(uint32_t*)&t;
}
__device__ __forceinline__ uint32_t smem_u32(const void* p) {
    return (uint32_t)__cvta_generic_to_shared(p);
}

// ============================================================
// fp32 -> fp16 convert, 8 elem/thread.
// z=0: X (n8x chunks). z=1..4: weights (n8w chunks each).
// ============================================================
__global__ __launch_bounds__(256) void cvt5_kernel(
    const float* __restrict__ x,
    const float* __restrict__ w0, const float* __restrict__ w1,
    const float* __restrict__ w2, const float* __restrict__ w3,
    __half* __restrict__ xo, __half* __restrict__ wo_,
    int n8x, int n8w)
{
    int i = blockIdx.x * 256 + threadIdx.x;
    int z = blockIdx.y;
    int lim = (z == 0) ? n8x : n8w;
    if (i >= lim) return;
    const float* in = (z == 0) ? x : (z == 1) ? w0 : (z == 2) ? w1 : (z == 3) ? w2 : w3;
    __half* o = (z == 0) ? xo : (wo_ + (size_t)(z-1) * WSZ);
    float4 a = ((const float4*)in)[2*i];
    float4 b = ((const float4*)in)[2*i+1];
    uint4 r;
    r.x = packh(a.x, a.y); r.y = packh(a.z, a.w);
    r.z = packh(b.x, b.y); r.w = packh(b.z, b.w);
    ((uint4*)o)[i] = r;
}

// ============================================================
// Persistent plain-fp16 mma.sync GEMM: C = A @ B, BK=64,
// 2-stage cp.async ring across tiles, 2x4 warp grid, 2 CTAs/SM.
// fused: z=0 rope+scale (Q), z=1 rope (K), z=2 plain (V); else fp32 out
// ============================================================
#define GBM 128
#define GBN 128
#define GBK 64
#define APAD 72
#define BPAD 136
#define SAB (GBM*APAD*2)            // 18432
#define SBB (GBK*BPAD*2)            // 17408
#define STAGE (SAB + SBB)           // 35840
#define GEMM_SMEM (2*STAGE)         // 71680 -> 2 CTAs/SM
#define CPT 32
#define TPZ (MROWS/GBM * DIM/GBN)   // 512

__global__ __launch_bounds__(256, 2) void gemm_fp16(
    const __half* __restrict__ A,
    const __half* __restrict__ B,
    __half* __restrict__ Qh, __half* __restrict__ Kh, __half* __restrict__ Vh,
    float* __restrict__ Cout,
    const float* __restrict__ fcos, const float* __restrict__ fsin,
    int fused, int ntiles)
{
    extern __shared__ char smraw[];
    const uint32_t sb = smem_u32(smraw);

    const int tid  = threadIdx.x;
    const int bid  = blockIdx.x;
    const int G    = gridDim.x;
    const int warp = tid >> 5, lane = tid & 31;
    const int wm = warp >> 2, wn = warp & 3;   // 2x4 grid, warp tile 64x32

    auto issue_chunk = [&](int myc) {
        int t = bid + (myc >> 5) * G;
        if (t >= ntiles) return;
        int z   = t / TPZ;
        int rem = t - z * TPZ;
        int row0 = (rem >> 4) * GBM;
        int col0 = (rem & 15) * GBN;
        const __half* bp = B + (size_t)z * WSZ;
        const uint32_t base = sb + (uint32_t)(myc & 1) * STAGE;
        const int k0 = (myc & (CPT-1)) * GBK;
        for (int idx = tid; idx < 1024; idx += 256) {
            int r = idx >> 3, o = (idx & 7) * 8;
            cp16(base + (uint32_t)(r * APAD + o) * 2,
                 A + (size_t)(row0 + r) * DIM + k0 + o);
        }
        for (int idx = tid; idx < 1024; idx += 256) {
            int r = idx >> 4, o = (idx & 15) * 8;
            cp16(base + SAB + (uint32_t)(r * BPAD + o) * 2,
                 bp + (size_t)(k0 + r) * DIM + col0 + o);
        }
    };

    issue_chunk(0);
    asm volatile("cp.async.commit_group;\n");
    issue_chunk(1);
    asm volatile("cp.async.commit_group;\n");

    const int arow  = (lane & 7) + ((lane >> 3) & 1) * 8;
    const int acol8 = (lane >> 4) * 8;
    const int brow8 = (lane & 7) + ((lane >> 3) & 1) * 8;
    const int bnc8  = (lane >> 4) * 8;
    const float qscale = 0.08838834764831845f;

    int myc = 0;
    for (int t = bid; t < ntiles; t += G) {
        const int z   = t / TPZ;
        const int rem = t - z * TPZ;
        const int row0 = (rem >> 4) * GBM;
        const int col0 = (rem & 15) * GBN;
        const int mode = fused ? z : 3;

        float acc[4][4][4];
#pragma unroll
        for (int i = 0; i < 4; i++)
#pragma unroll
            for (int j = 0; j < 4; j++)
#pragma unroll
                for (int r = 0; r < 4; r++) acc[i][j][r] = 0.f;

        for (int i = 0; i < CPT; i++, myc++) {
            asm volatile("cp.async.wait_group 1;\n");
            __syncthreads();

            const uint32_t base = sb + (uint32_t)(myc & 1) * STAGE;
            const uint32_t bA = base, bB = base + SAB;

#pragma unroll
            for (int ks = 0; ks < 4; ks++) {
                const int acol = ks * 16 + acol8;
                const int brow = ks * 16 + brow8;
                uint32_t bfr[4][2];
#pragma unroll
                for (int hh = 0; hh < 2; hh++) {
                    int nc = wn * 32 + hh * 16 + bnc8;
                    uint32_t t4[4];
                    ldsm4t(t4, bB + (uint32_t)(brow * BPAD + nc) * 2);
                    bfr[hh*2][0] = t4[0]; bfr[hh*2][1] = t4[1];
                    bfr[hh*2+1][0] = t4[2]; bfr[hh*2+1][1] = t4[3];
                }
                uint32_t af[4][4];
#pragma unroll
                for (int mt = 0; mt < 4; mt++)
                    ldsm4(af[mt], bA + (uint32_t)((wm*64 + mt*16 + arow) * APAD + acol) * 2);
#pragma unroll
                for (int mt = 0; mt < 4; mt++)
#pragma unroll
                    for (int nt = 0; nt < 4; nt++)
                        mma16816(acc[mt][nt], af[mt], bfr[nt]);
            }

            __syncthreads();
            issue_chunk(myc + 2);
            asm volatile("cp.async.commit_group;\n");
        }

        // ---- fused epilogue ----
#pragma unroll
        for (int mt = 0; mt < 4; mt++) {
#pragma unroll
            for (int nt = 0; nt < 4; nt++) {
                int r = row0 + wm * 64 + mt * 16 + (lane >> 2);
                int c = col0 + wn * 32 + nt * 8 + (lane & 3) * 2;
                float a0 = acc[mt][nt][0], a1 = acc[mt][nt][1];
                float a2 = acc[mt][nt][2], a3 = acc[mt][nt][3];
                size_t o0 = (size_t)r * DIM + c, o1 = (size_t)(r + 8) * DIM + c;
                if (mode == 3) {
                    *(float2*)(Cout + o0) = make_float2(a0, a1);
                    *(float2*)(Cout + o1) = make_float2(a2, a3);
                } else if (mode == 2) {
                    *(uint32_t*)(Vh + o0) = packh(a0, a1);
                    *(uint32_t*)(Vh + o1) = packh(a2, a3);
                } else {
                    int i2 = (c & (HD - 1)) >> 1;
                    int s0 = r & (SEQ - 1), s1 = (r + 8) & (SEQ - 1);
                    float c0 = fcos[s0 * (HD/2) + i2], n0 = fsin[s0 * (HD/2) + i2];
                    float c1 = fcos[s1 * (HD/2) + i2], n1 = fsin[s1 * (HD/2) + i2];
                    float t0 = a0 * c0 - a1 * n0, t1 = a0 * n0 + a1 * c0;
                    float t2 = a2 * c1 - a3 * n1, t3 = a2 * n1 + a3 * c1;
                    __half* dst = Kh;
                    if (mode == 0) {
                        t0 *= qscale; t1 *= qscale; t2 *= qscale; t3 *= qscale;
                        dst = Qh;
                    }
                    *(uint32_t*)(dst + o0) = packh(t0, t1);
                    *(uint32_t*)(dst + o1) = packh(t2, t3);
                }
            }
        }
    }
}

// ============================================================
// Plain-fp16 causal flash attention, 64x64 tiles, mma.sync.
// Q, K, V, P all plain fp16 (error budget verified). 3 CTAs/SM.
// ============================================================
#define AQ  64
#define APD 136
#define TILE_E (AQ*APD)
#define ATTN_SMEM (3*TILE_E*2)     // Q,K,V = 52224

__global__ __launch_bounds__(128, 3) void attn_tc_kernel(
    const __half* __restrict__ Qg, const __half* __restrict__ Kg,
    const __half* __restrict__ Vg, __half* __restrict__ Og)
{
    extern __shared__ __half sm[];
    __half* sQ = sm;
    __half* sK = sQ + TILE_E;
    __half* sV = sK + TILE_E;
    const uint32_t uQ = smem_u32(sQ);
    const uint32_t uK = smem_u32(sK);
    const uint32_t uV = smem_u32(sV);

    const int tid = threadIdx.x, warp = tid >> 5, lane = tid & 31;
    const int qt = (int)(gridDim.x - 1 - blockIdx.x);
    const int h = blockIdx.y, b = blockIdx.z;
    const int q0 = qt * AQ;
    const size_t rowbase = (size_t)b * SEQ;
    const size_t colh = (size_t)h * HD;

#define LOADTILE(dstu, src, r0) do {                                           \
    for (int c0_ = tid; c0_ < 1024; c0_ += 128) {                              \
        int r_ = c0_ >> 4, o_ = (c0_ & 15) * 8;                                \
        cp16((dstu) + (r_*APD + o_)*2,                                         \
             (src) + (rowbase + (r0) + r_)*DIM + colh + o_);                   \
    } } while (0)

    LOADTILE(uQ, Qg, q0);
    LOADTILE(uK, Kg, 0);
    asm volatile("cp.async.commit_group;\n");

    float o[16][4];
#pragma unroll
    for (int nt = 0; nt < 16; nt++)
#pragma unroll
        for (int r = 0; r < 4; r++) o[nt][r] = 0.f;
    float m0 = -INFINITY, m1 = -INFINITY, l0 = 0.f, l1 = 0.f;

    const int nkv = qt + 1;
    const int arow = (lane & 7) + ((lane >> 3) & 1) * 8;
    const int acol8 = (lane >> 4) * 8;
    const int bro8 = (lane & 7) + ((lane >> 4) << 3);
    const int bco8 = ((lane >> 3) & 1) * 8;
    const int vro8 = (lane & 7) + ((lane >> 3) & 1) * 8;
    const int vco8 = (lane >> 4) * 8;

    for (int kt = 0; kt < nkv; kt++) {
        asm volatile("cp.async.wait_group 0;\n");
        __syncthreads();

        LOADTILE(uV, Vg, kt*AQ);
        asm volatile("cp.async.commit_group;\n");

        // ---- S = Q K^T (single pass) ----
        float s[8][4];
#pragma unroll
        for (int t = 0; t < 8; t++)
#pragma unroll
            for (int r = 0; r < 4; r++) s[t][r] = 0.f;

#pragma unroll
        for (int ks = 0; ks < 8; ks++) {
            uint32_t q4[4];
            uint32_t aoff = ((warp*16 + arow)*APD + ks*16 + acol8)*2;
            ldsm4(q4, uQ + aoff);
#pragma unroll
            for (int bt = 0; bt < 4; bt++) {
                uint32_t k4[4];
                uint32_t boff = ((bt*16 + bro8)*APD + ks*16 + bco8)*2;
                ldsm4(k4, uK + boff);
                mma16816(s[2*bt],   q4, k4);
                mma16816(s[2*bt+1], q4, k4+2);
            }
        }

        if (kt == qt) {
            int rl0 = warp*16 + (lane >> 2);
            int cb = (lane & 3) * 2;
#pragma unroll
            for (int t = 0; t < 8; t++) {
                int c0 = t*8 + cb, c1 = c0 + 1;
                if (c0 > rl0)     s[t][0] = -INFINITY;
                if (c1 > rl0)     s[t][1] = -INFINITY;
                if (c0 > rl0 + 8) s[t][2] = -INFINITY;
                if (c1 > rl0 + 8) s[t][3] = -INFINITY;
            }
        }

        float mt0 = -INFINITY, mt1 = -INFINITY;
#pragma unroll
        for (int t = 0; t < 8; t++) {
            mt0 = fmaxf(mt0, fmaxf(s[t][0], s[t][1]));
            mt1 = fmaxf(mt1, fmaxf(s[t][2], s[t][3]));
        }
        mt0 = fmaxf(mt0, __shfl_xor_sync(0xffffffffu, mt0, 1));
        mt0 = fmaxf(mt0, __shfl_xor_sync(0xffffffffu, mt0, 2));
        mt1 = fmaxf(mt1, __shfl_xor_sync(0xffffffffu, mt1, 1));
        mt1 = fmaxf(mt1, __shfl_xor_sync(0xffffffffu, mt1, 2));
        float mn0 = fmaxf(m0, mt0), mn1 = fmaxf(m1, mt1);
        float corr0 = __expf(m0 - mn0), corr1 = __expf(m1 - mn1);
        m0 = mn0; m1 = mn1;

        float p[8][4];
        float sum0 = 0.f, sum1 = 0.f;
#pragma unroll
        for (int t = 0; t < 8; t++) {
            p[t][0] = __expf(s[t][0] - mn0);
            p[t][1] = __expf(s[t][1] - mn0);
            p[t][2] = __expf(s[t][2] - mn1);
            p[t][3] = __expf(s[t][3] - mn1);
            sum0 += p[t][0] + p[t][1];
            sum1 += p[t][2] + p[t][3];
        }
        sum0 += __shfl_xor_sync(0xffffffffu, sum0, 1);
        sum0 += __shfl_xor_sync(0xffffffffu, sum0, 2);
        sum1 += __shfl_xor_sync(0xffffffffu, sum1, 1);
        sum1 += __shfl_xor_sync(0xffffffffu, sum1, 2);
        l0 = l0 * corr0 + sum0;
        l1 = l1 * corr1 + sum1;

        // pack P (plain fp16 A-fragments)
        uint32_t ph[4][4];
#pragma unroll
        for (int c = 0; c < 4; c++) {
            ph[c][0] = packh(p[2*c][0],   p[2*c][1]);
            ph[c][1] = packh(p[2*c][2],   p[2*c][3]);
            ph[c][2] = packh(p[2*c+1][0], p[2*c+1][1]);
            ph[c][3] = packh(p[2*c+1][2], p[2*c+1][3]);
        }

#pragma unroll
        for (int nt = 0; nt < 16; nt++) {
            o[nt][0] *= corr0; o[nt][1] *= corr0;
            o[nt][2] *= corr1; o[nt][3] *= corr1;
        }

        asm volatile("cp.async.wait_group 0;\n");
        __syncthreads();

        if (kt + 1 < nkv) {
            LOADTILE(uK, Kg, (kt+1)*AQ);
        }
        asm volatile("cp.async.commit_group;\n");

        // ---- O += P V (single pass) ----
#pragma unroll
        for (int c = 0; c < 4; c++) {
#pragma unroll
            for (int np = 0; np < 8; np++) {
                uint32_t v4[4];
                uint32_t voff = ((c*16 + vro8)*APD + np*16 + vco8)*2;
                ldsm4t(v4, uV + voff);
                mma16816(o[2*np],   ph[c], v4);
                mma16816(o[2*np+1], ph[c], v4+2);
            }
        }
    }

    float inv0 = 1.f / l0, inv1 = 1.f / l1;
    size_t r0g = rowbase + q0 + warp*16 + (lane >> 2);
    size_t cg  = colh + (lane & 3)*2;
#pragma unroll
    for (int nt = 0; nt < 16; nt++) {
        size_t off0 = r0g*DIM + cg + nt*8;
        size_t off1 = (r0g+8)*DIM + cg + nt*8;
        *(uint32_t*)(Og + off0) = packh(o[nt][0]*inv0, o[nt][1]*inv0);
        *(uint32_t*)(Og + off1) = packh(o[nt][2]*inv1, o[nt][3]*inv1);
    }
}

// ============================================================
extern "C" void kernel_launch(void* const* d_in, const int* in_sizes, int n_in,
                              void* d_out, int out_size)
{
    const float* x   = (const float*)d_in[0];
    const float* wq  = (const float*)d_in[1];
    const float* wk  = (const float*)d_in[2];
    const float* wv  = (const float*)d_in[3];
    const float* wo  = (const float*)d_in[4];
    const float* fco = (const float*)d_in[5];
    const float* fsi = (const float*)d_in[6];
    float* out = (float*)d_out;

    __half *X, *W, *Qh, *Kh, *Vh, *Oh;
    cudaGetSymbolAddress((void**)&X,  g_X);
    cudaGetSymbolAddress((void**)&W,  g_W);
    cudaGetSymbolAddress((void**)&Qh, g_Qh);
    cudaGetSymbolAddress((void**)&Kh, g_Kh);
    cudaGetSymbolAddress((void**)&Vh, g_Vh);
    cudaGetSymbolAddress((void**)&Oh, g_Oh);

    cudaFuncSetAttribute(gemm_fp16,
        cudaFuncAttributeMaxDynamicSharedMemorySize, GEMM_SMEM);
    cudaFuncSetAttribute(attn_tc_kernel,
        cudaFuncAttributeMaxDynamicSharedMemorySize, ATTN_SMEM);

    const int n8x = MROWS * DIM / 8;    // 1,048,576
    const int n8w = DIM * DIM / 8;      //   524,288

    dim3 cgrid((n8x + 255)/256, 5);
    cvt5_kernel<<<cgrid, 256>>>(x, wq, wk, wv, wo, X, W, n8x, n8w);

    // persistent fused QKV projection
    gemm_fp16<<<296, 256, GEMM_SMEM>>>(
        X, W, Qh, Kh, Vh,
        nullptr, fco, fsi, 1, 3*TPZ);

    dim3 agrid(SEQ / AQ, NH, BATCH);       // (32, 16, 2)
    attn_tc_kernel<<<agrid, 128, ATTN_SMEM>>>(Qh, Kh, Vh, Oh);

    // persistent output projection (fp32 store)
    gemm_fp16<<<296, 256, GEMM_SMEM>>>(
        Oh, W + 3*WSZ, nullptr, nullptr, nullptr,
        out, fco, fsi, 0, TPZ);
}

// round 14
// speedup vs baseline: 1.7403x; 1.0095x over previous
#include <cuda_runtime.h>
#include <cuda_fp16.h>
#include <math.h>
#include <stdint.h>

#define DIM   2048
#define NH    16
#define HD    128
#define SEQ   2048
#define BATCH 2
#define MROWS (BATCH*SEQ)   // 4096
#define WSZ   ((size_t)DIM*DIM)

// ---- scratch (device globals, all fp16) ----
__device__ __half g_X [(size_t)MROWS*DIM];
__device__ __half g_W[4][WSZ];            // plain fp16, [K,N]
__device__ __half g_Qh [(size_t)MROWS*DIM];
__device__ __half g_Kh [(size_t)MROWS*DIM];
__device__ __half g_Vh [(size_t)MROWS*DIM];
__device__ __half g_Oh [(size_t)MROWS*DIM];

// ---------- PTX helpers ----------
__device__ __forceinline__ void cp16(uint32_t dst, const void* src) {
    asm volatile("cp.async.cg.shared.global [%0], [%1], 16;\n" :: "r"(dst), "l"(src));
}
__device__ __forceinline__ void ldsm4(uint32_t* r, uint32_t a) {
    asm volatile("ldmatrix.sync.aligned.m8n8.x4.shared.b16 {%0,%1,%2,%3}, [%4];\n"
        : "=r"(r[0]), "=r"(r[1]), "=r"(r[2]), "=r"(r[3]) : "r"(a));
}
__device__ __forceinline__ void ldsm4t(uint32_t* r, uint32_t a) {
    asm volatile("ldmatrix.sync.aligned.m8n8.x4.trans.shared.b16 {%0,%1,%2,%3}, [%4];\n"
        : "=r"(r[0]), "=r"(r[1]), "=r"(r[2]), "=r"(r[3]) : "r"(a));
}
__device__ __forceinline__ void mma16816(float* c, const uint32_t* a, const uint32_t* b) {
    asm volatile("mma.sync.aligned.m16n8k16.row.col.f32.f16.f16.f32 "
        "{%0,%1,%2,%3}, {%4,%5,%6,%7}, {%8,%9}, {%0,%1,%2,%3};\n"
        : "+f"(c[0]), "+f"(c[1]), "+f"(c[2]), "+f"(c[3])
        : "r"(a[0]), "r"(a[1]), "r"(a[2]), "r"(a[3]), "r"(b[0]), "r"(b[1]));
}
__device__ __forceinline__ uint32_t packh(float x, float y) {
    __half2 t = __floats2half2_rn(x, y);
    return *(uint32_t*)&t;
}
__device__ __forceinline__ uint32_t smem_u32(const void* p) {
    return (uint32_t)__cvta_generic_to_shared(p);
}

// ============================================================
// fp32 -> fp16 convert, 8 elem/thread.
// z=0: X (n8x chunks). z=1..4: weights (n8w chunks each).
// ============================================================
__global__ __launch_bounds__(256) void cvt5_kernel(
    const float* __restrict__ x,
    const float* __restrict__ w0, const float* __restrict__ w1,
    const float* __restrict__ w2, const float* __restrict__ w3,
    __half* __restrict__ xo, __half* __restrict__ wo_,
    int n8x, int n8w)
{
    int i = blockIdx.x * 256 + threadIdx.x;
    int z = blockIdx.y;
    int lim = (z == 0) ? n8x : n8w;
    if (i >= lim) return;
    const float* in = (z == 0) ? x : (z == 1) ? w0 : (z == 2) ? w1 : (z == 3) ? w2 : w3;
    __half* o = (z == 0) ? xo : (wo_ + (size_t)(z-1) * WSZ);
    float4 a = ((const float4*)in)[2*i];
    float4 b = ((const float4*)in)[2*i+1];
    uint4 r;
    r.x = packh(a.x, a.y); r.y = packh(a.z, a.w);
    r.z = packh(b.x, b.y); r.w = packh(b.z, b.w);
    ((uint4*)o)[i] = r;
}

// ============================================================
// Persistent plain-fp16 mma.sync GEMM: C = A @ B, BK=64,
// 3-stage cp.async ring across tiles, one sync per chunk,
// ordering: wait -> sync -> issue -> compute (race-free).
// 2x4 warp grid, 2 CTAs/SM.
// fused: z=0 rope+scale (Q), z=1 rope (K), z=2 plain (V); else fp32 out
// ============================================================
#define GBM 128
#define GBN 128
#define GBK 64
#define APAD 72
#define BPAD 136
#define SAB (GBM*APAD*2)            // 18432
#define SBB (GBK*BPAD*2)            // 17408
#define STAGE (SAB + SBB)           // 35840
#define GEMM_SMEM (3*STAGE)         // 107520 -> 2 CTAs/SM
#define CPT 32
#define TPZ (MROWS/GBM * DIM/GBN)   // 512

__global__ __launch_bounds__(256, 2) void gemm_fp16(
    const __half* __restrict__ A,
    const __half* __restrict__ B,
    __half* __restrict__ Qh, __half* __restrict__ Kh, __half* __restrict__ Vh,
    float* __restrict__ Cout,
    const float* __restrict__ fcos, const float* __restrict__ fsin,
    int fused, int ntiles)
{
    extern __shared__ char smraw[];
    const uint32_t sb = smem_u32(smraw);

    const int tid  = threadIdx.x;
    const int bid  = blockIdx.x;
    const int G    = gridDim.x;
    const int warp = tid >> 5, lane = tid & 31;
    const int wm = warp >> 2, wn = warp & 3;   // 2x4 grid, warp tile 64x32

    // issue chunk #myc of this CTA's sequence into buffer myc%3
    auto issue_chunk = [&](int myc) {
        int t = bid + (myc >> 5) * G;
        if (t >= ntiles) return;
        int z   = t / TPZ;
        int rem = t - z * TPZ;
        int row0 = (rem >> 4) * GBM;
        int col0 = (rem & 15) * GBN;
        const __half* bp = B + (size_t)z * WSZ;
        const uint32_t base = sb + (uint32_t)(myc % 3) * STAGE;
        const int k0 = (myc & (CPT-1)) * GBK;
        for (int idx = tid; idx < 1024; idx += 256) {
            int r = idx >> 3, o = (idx & 7) * 8;
            cp16(base + (uint32_t)(r * APAD + o) * 2,
                 A + (size_t)(row0 + r) * DIM + k0 + o);
        }
        for (int idx = tid; idx < 1024; idx += 256) {
            int r = idx >> 4, o = (idx & 15) * 8;
            cp16(base + SAB + (uint32_t)(r * BPAD + o) * 2,
                 bp + (size_t)(k0 + r) * DIM + col0 + o);
        }
    };

    issue_chunk(0);
    asm volatile("cp.async.commit_group;\n");
    issue_chunk(1);
    asm volatile("cp.async.commit_group;\n");

    const int arow  = (lane & 7) + ((lane >> 3) & 1) * 8;
    const int acol8 = (lane >> 4) * 8;
    const int brow8 = (lane & 7) + ((lane >> 3) & 1) * 8;
    const int bnc8  = (lane >> 4) * 8;
    const float qscale = 0.08838834764831845f;

    int myc = 0;
    for (int t = bid; t < ntiles; t += G) {
        const int z   = t / TPZ;
        const int rem = t - z * TPZ;
        const int row0 = (rem >> 4) * GBM;
        const int col0 = (rem & 15) * GBN;
        const int mode = fused ? z : 3;

        float acc[4][4][4];
#pragma unroll
        for (int i = 0; i < 4; i++)
#pragma unroll
            for (int j = 0; j < 4; j++)
#pragma unroll
                for (int r = 0; r < 4; r++) acc[i][j][r] = 0.f;

        for (int i = 0; i < CPT; i++, myc++) {
            asm volatile("cp.async.wait_group 1;\n");  // own groups: chunk myc landed
            __syncthreads();                            // all threads waited -> data visible;
                                                        // also: all reads of chunk myc-1 done
            issue_chunk(myc + 2);                       // buffer (myc+2)%3 == (myc-1)%3, free
            asm volatile("cp.async.commit_group;\n");

            const uint32_t base = sb + (uint32_t)(myc % 3) * STAGE;
            const uint32_t bA = base, bB = base + SAB;

#pragma unroll
            for (int ks = 0; ks < 4; ks++) {
                const int acol = ks * 16 + acol8;
                const int brow = ks * 16 + brow8;
                uint32_t bfr[4][2];
#pragma unroll
                for (int hh = 0; hh < 2; hh++) {
                    int nc = wn * 32 + hh * 16 + bnc8;
                    uint32_t t4[4];
                    ldsm4t(t4, bB + (uint32_t)(brow * BPAD + nc) * 2);
                    bfr[hh*2][0] = t4[0]; bfr[hh*2][1] = t4[1];
                    bfr[hh*2+1][0] = t4[2]; bfr[hh*2+1][1] = t4[3];
                }
                uint32_t af[4][4];
#pragma unroll
                for (int mt = 0; mt < 4; mt++)
                    ldsm4(af[mt], bA + (uint32_t)((wm*64 + mt*16 + arow) * APAD + acol) * 2);
#pragma unroll
                for (int mt = 0; mt < 4; mt++)
#pragma unroll
                    for (int nt = 0; nt < 4; nt++)
                        mma16816(acc[mt][nt], af[mt], bfr[nt]);
            }
        }

        // ---- fused epilogue (registers+global only) ----
#pragma unroll
        for (int mt = 0; mt < 4; mt++) {
#pragma unroll
            for (int nt = 0; nt < 4; nt++) {
                int r = row0 + wm * 64 + mt * 16 + (lane >> 2);
                int c = col0 + wn * 32 + nt * 8 + (lane & 3) * 2;
                float a0 = acc[mt][nt][0], a1 = acc[mt][nt][1];
                float a2 = acc[mt][nt][2], a3 = acc[mt][nt][3];
                size_t o0 = (size_t)r * DIM + c, o1 = (size_t)(r + 8) * DIM + c;
                if (mode == 3) {
                    *(float2*)(Cout + o0) = make_float2(a0, a1);
                    *(float2*)(Cout + o1) = make_float2(a2, a3);
                } else if (mode == 2) {
                    *(uint32_t*)(Vh + o0) = packh(a0, a1);
                    *(uint32_t*)(Vh + o1) = packh(a2, a3);
                } else {
                    int i2 = (c & (HD - 1)) >> 1;
                    int s0 = r & (SEQ - 1), s1 = (r + 8) & (SEQ - 1);
                    float c0 = fcos[s0 * (HD/2) + i2], n0 = fsin[s0 * (HD/2) + i2];
                    float c1 = fcos[s1 * (HD/2) + i2], n1 = fsin[s1 * (HD/2) + i2];
                    float t0 = a0 * c0 - a1 * n0, t1 = a0 * n0 + a1 * c0;
                    float t2 = a2 * c1 - a3 * n1, t3 = a2 * n1 + a3 * c1;
                    __half* dst = Kh;
                    if (mode == 0) {
                        t0 *= qscale; t1 *= qscale; t2 *= qscale; t3 *= qscale;
                        dst = Qh;
                    }
                    *(uint32_t*)(dst + o0) = packh(t0, t1);
                    *(uint32_t*)(dst + o1) = packh(t2, t3);
                }
            }
        }
    }
}

// ============================================================
// Plain-fp16 causal flash attention, 64x64 tiles, 3 CTAs/SM.
// ============================================================
#define AQ  64
#define APD 136
#define TILE_E (AQ*APD)
#define ATTN_SMEM (3*TILE_E*2)     // Q,K,V = 52224

__global__ __launch_bounds__(128, 3) void attn_tc_kernel(
    const __half* __restrict__ Qg, const __half* __restrict__ Kg,
    const __half* __restrict__ Vg, __half* __restrict__ Og)
{
    extern __shared__ __half sm[];
    __half* sQ = sm;
    __half* sK = sQ + TILE_E;
    __half* sV = sK + TILE_E;
    const uint32_t uQ = smem_u32(sQ);
    const uint32_t uK = smem_u32(sK);
    const uint32_t uV = smem_u32(sV);

    const int tid = threadIdx.x, warp = tid >> 5, lane = tid & 31;
    const int qt = (int)(gridDim.x - 1 - blockIdx.x);
    const int h = blockIdx.y, b = blockIdx.z;
    const int q0 = qt * AQ;
    const size_t rowbase = (size_t)b * SEQ;
    const size_t colh = (size_t)h * HD;

#define LOADTILE(dstu, src, r0) do {                                           \
    for (int c0_ = tid; c0_ < 1024; c0_ += 128) {                              \
        int r_ = c0_ >> 4, o_ = (c0_ & 15) * 8;                                \
        cp16((dstu) + (r_*APD + o_)*2,                                         \
             (src) + (rowbase + (r0) + r_)*DIM + colh + o_);                   \
    } } while (0)

    LOADTILE(uQ, Qg, q0);
    LOADTILE(uK, Kg, 0);
    asm volatile("cp.async.commit_group;\n");

    float o[16][4];
#pragma unroll
    for (int nt = 0; nt < 16; nt++)
#pragma unroll
        for (int r = 0; r < 4; r++) o[nt][r] = 0.f;
    float m0 = -INFINITY, m1 = -INFINITY, l0 = 0.f, l1 = 0.f;

    const int nkv = qt + 1;
    const int arow = (lane & 7) + ((lane >> 3) & 1) * 8;
    const int acol8 = (lane >> 4) * 8;
    const int bro8 = (lane & 7) + ((lane >> 4) << 3);
    const int bco8 = ((lane >> 3) & 1) * 8;
    const int vro8 = (lane & 7) + ((lane >> 3) & 1) * 8;
    const int vco8 = (lane >> 4) * 8;

    for (int kt = 0; kt < nkv; kt++) {
        asm volatile("cp.async.wait_group 0;\n");
        __syncthreads();

        LOADTILE(uV, Vg, kt*AQ);
        asm volatile("cp.async.commit_group;\n");

        float s[8][4];
#pragma unroll
        for (int t = 0; t < 8; t++)
#pragma unroll
            for (int r = 0; r < 4; r++) s[t][r] = 0.f;

#pragma unroll
        for (int ks = 0; ks < 8; ks++) {
            uint32_t q4[4];
            uint32_t aoff = ((warp*16 + arow)*APD + ks*16 + acol8)*2;
            ldsm4(q4, uQ + aoff);
#pragma unroll
            for (int bt = 0; bt < 4; bt++) {
                uint32_t k4[4];
                uint32_t boff = ((bt*16 + bro8)*APD + ks*16 + bco8)*2;
                ldsm4(k4, uK + boff);
                mma16816(s[2*bt],   q4, k4);
                mma16816(s[2*bt+1], q4, k4+2);
            }
        }

        if (kt == qt) {
            int rl0 = warp*16 + (lane >> 2);
            int cb = (lane & 3) * 2;
#pragma unroll
            for (int t = 0; t < 8; t++) {
                int c0 = t*8 + cb, c1 = c0 + 1;
                if (c0 > rl0)     s[t][0] = -INFINITY;
                if (c1 > rl0)     s[t][1] = -INFINITY;
                if (c0 > rl0 + 8) s[t][2] = -INFINITY;
                if (c1 > rl0 + 8) s[t][3] = -INFINITY;
            }
        }

        float mt0 = -INFINITY, mt1 = -INFINITY;
#pragma unroll
        for (int t = 0; t < 8; t++) {
            mt0 = fmaxf(mt0, fmaxf(s[t][0], s[t][1]));
            mt1 = fmaxf(mt1, fmaxf(s[t][2], s[t][3]));
        }
        mt0 = fmaxf(mt0, __shfl_xor_sync(0xffffffffu, mt0, 1));
        mt0 = fmaxf(mt0, __shfl_xor_sync(0xffffffffu, mt0, 2));
        mt1 = fmaxf(mt1, __shfl_xor_sync(0xffffffffu, mt1, 1));
        mt1 = fmaxf(mt1, __shfl_xor_sync(0xffffffffu, mt1, 2));
        float mn0 = fmaxf(m0, mt0), mn1 = fmaxf(m1, mt1);
        float corr0 = __expf(m0 - mn0), corr1 = __expf(m1 - mn1);
        m0 = mn0; m1 = mn1;

        float p[8][4];
        float sum0 = 0.f, sum1 = 0.f;
#pragma unroll
        for (int t = 0; t < 8; t++) {
            p[t][0] = __expf(s[t][0] - mn0);
            p[t][1] = __expf(s[t][1] - mn0);
            p[t][2] = __expf(s[t][2] - mn1);
            p[t][3] = __expf(s[t][3] - mn1);
            sum0 += p[t][0] + p[t][1];
            sum1 += p[t][2] + p[t][3];
        }
        sum0 += __shfl_xor_sync(0xffffffffu, sum0, 1);
        sum0 += __shfl_xor_sync(0xffffffffu, sum0, 2);
        sum1 += __shfl_xor_sync(0xffffffffu, sum1, 1);
        sum1 += __shfl_xor_sync(0xffffffffu, sum1, 2);
        l0 = l0 * corr0 + sum0;
        l1 = l1 * corr1 + sum1;

        uint32_t ph[4][4];
#pragma unroll
        for (int c = 0; c < 4; c++) {
            ph[c][0] = packh(p[2*c][0],   p[2*c][1]);
            ph[c][1] = packh(p[2*c][2],   p[2*c][3]);
            ph[c][2] = packh(p[2*c+1][0], p[2*c+1][1]);
            ph[c][3] = packh(p[2*c+1][2], p[2*c+1][3]);
        }

#pragma unroll
        for (int nt = 0; nt < 16; nt++) {
            o[nt][0] *= corr0; o[nt][1] *= corr0;
            o[nt][2] *= corr1; o[nt][3] *= corr1;
        }

        asm volatile("cp.async.wait_group 0;\n");
        __syncthreads();

        if (kt + 1 < nkv) {
            LOADTILE(uK, Kg, (kt+1)*AQ);
        }
        asm volatile("cp.async.commit_group;\n");

#pragma unroll
        for (int c = 0; c < 4; c++) {
#pragma unroll
            for (int np = 0; np < 8; np++) {
                uint32_t v4[4];
                uint32_t voff = ((c*16 + vro8)*APD + np*16 + vco8)*2;
                ldsm4t(v4, uV + voff);
                mma16816(o[2*np],   ph[c], v4);
                mma16816(o[2*np+1], ph[c], v4+2);
            }
        }
    }

    float inv0 = 1.f / l0, inv1 = 1.f / l1;
    size_t r0g = rowbase + q0 + warp*16 + (lane >> 2);
    size_t cg  = colh + (lane & 3)*2;
#pragma unroll
    for (int nt = 0; nt < 16; nt++) {
        size_t off0 = r0g*DIM + cg + nt*8;
        size_t off1 = (r0g+8)*DIM + cg + nt*8;
        *(uint32_t*)(Og + off0) = packh(o[nt][0]*inv0, o[nt][1]*inv0);
        *(uint32_t*)(Og + off1) = packh(o[nt][2]*inv1, o[nt][3]*inv1);
    }
}

// ============================================================
extern "C" void kernel_launch(void* const* d_in, const int* in_sizes, int n_in,
                              void* d_out, int out_size)
{
    const float* x   = (const float*)d_in[0];
    const float* wq  = (const float*)d_in[1];
    const float* wk  = (const float*)d_in[2];
    const float* wv  = (const float*)d_in[3];
    const float* wo  = (const float*)d_in[4];
    const float* fco = (const float*)d_in[5];
    const float* fsi = (const float*)d_in[6];
    float* out = (float*)d_out;

    __half *X, *W, *Qh, *Kh, *Vh, *Oh;
    cudaGetSymbolAddress((void**)&X,  g_X);
    cudaGetSymbolAddress((void**)&W,  g_W);
    cudaGetSymbolAddress((void**)&Qh, g_Qh);
    cudaGetSymbolAddress((void**)&Kh, g_Kh);
    cudaGetSymbolAddress((void**)&Vh, g_Vh);
    cudaGetSymbolAddress((void**)&Oh, g_Oh);

    cudaFuncSetAttribute(gemm_fp16,
        cudaFuncAttributeMaxDynamicSharedMemorySize, GEMM_SMEM);
    cudaFuncSetAttribute(attn_tc_kernel,
        cudaFuncAttributeMaxDynamicSharedMemorySize, ATTN_SMEM);

    const int n8x = MROWS * DIM / 8;    // 1,048,576
    const int n8w = DIM * DIM / 8;      //   524,288

    dim3 cgrid((n8x + 255)/256, 5);
    cvt5_kernel<<<cgrid, 256>>>(x, wq, wk, wv, wo, X, W, n8x, n8w);

    // persistent fused QKV projection
    gemm_fp16<<<296, 256, GEMM_SMEM>>>(
        X, W, Qh, Kh, Vh,
        nullptr, fco, fsi, 1, 3*TPZ);

    dim3 agrid(SEQ / AQ, NH, BATCH);       // (32, 16, 2)
    attn_tc_kernel<<<agrid, 128, ATTN_SMEM>>>(Qh, Kh, Vh, Oh);

    // persistent output projection (fp32 store)
    gemm_fp16<<<296, 256, GEMM_SMEM>>>(
        Oh, W + 3*WSZ, nullptr, nullptr, nullptr,
        out, fco, fsi, 0, TPZ);
}

// round 15
// speedup vs baseline: 1.7748x; 1.0198x over previous
#include <cuda_runtime.h>
#include <cuda_fp16.h>
#include <math.h>
#include <stdint.h>

#define DIM   2048
#define NH    16
#define HD    128
#define SEQ   2048
#define BATCH 2
#define MROWS (BATCH*SEQ)   // 4096
#define WSZ   ((size_t)DIM*DIM)

// ---- scratch (device globals, all fp16) ----
__device__ __half g_X [(size_t)MROWS*DIM];
__device__ __half g_W[4][WSZ];            // plain fp16, [K,N]; Wq pre-scaled by 1/sqrt(HD)
__device__ __half g_Qh [(size_t)MROWS*DIM];
__device__ __half g_Kh [(size_t)MROWS*DIM];
__device__ __half g_Vh [(size_t)MROWS*DIM];
__device__ __half g_Oh [(size_t)MROWS*DIM];

// ---------- PTX helpers ----------
__device__ __forceinline__ void cp16(uint32_t dst, const void* src) {
    asm volatile("cp.async.cg.shared.global [%0], [%1], 16;\n" :: "r"(dst), "l"(src));
}
__device__ __forceinline__ void ldsm4(uint32_t* r, uint32_t a) {
    asm volatile("ldmatrix.sync.aligned.m8n8.x4.shared.b16 {%0,%1,%2,%3}, [%4];\n"
        : "=r"(r[0]), "=r"(r[1]), "=r"(r[2]), "=r"(r[3]) : "r"(a));
}
__device__ __forceinline__ void ldsm4t(uint32_t* r, uint32_t a) {
    asm volatile("ldmatrix.sync.aligned.m8n8.x4.trans.shared.b16 {%0,%1,%2,%3}, [%4];\n"
        : "=r"(r[0]), "=r"(r[1]), "=r"(r[2]), "=r"(r[3]) : "r"(a));
}
__device__ __forceinline__ void mma16816(float* c, const uint32_t* a, const uint32_t* b) {
    asm volatile("mma.sync.aligned.m16n8k16.row.col.f32.f16.f16.f32 "
        "{%0,%1,%2,%3}, {%4,%5,%6,%7}, {%8,%9}, {%0,%1,%2,%3};\n"
        : "+f"(c[0]), "+f"(c[1]), "+f"(c[2]), "+f"(c[3])
        : "r"(a[0]), "r"(a[1]), "r"(a[2]), "r"(a[3]), "r"(b[0]), "r"(b[1]));
}
__device__ __forceinline__ uint32_t packh(float x, float y) {
    __half2 t = __floats2half2_rn(x, y);
    return *(uint32_t*)&t;
}
__device__ __forceinline__ uint32_t smem_u32(const void* p) {
    return (uint32_t)__cvta_generic_to_shared(p);
}

// ============================================================
// fp32 -> fp16 convert, 8 elem/thread.
// z=0: X. z=1..4: weights (z=1 Wq scaled by 1/sqrt(HD)).
// ============================================================
__global__ __launch_bounds__(256) void cvt5_kernel(
    const float* __restrict__ x,
    const float* __restrict__ w0, const float* __restrict__ w1,
    const float* __restrict__ w2, const float* __restrict__ w3,
    __half* __restrict__ xo, __half* __restrict__ wo_,
    int n8x, int n8w)
{
    int i = blockIdx.x * 256 + threadIdx.x;
    int z = blockIdx.y;
    int lim = (z == 0) ? n8x : n8w;
    if (i >= lim) return;
    const float* in = (z == 0) ? x : (z == 1) ? w0 : (z == 2) ? w1 : (z == 3) ? w2 : w3;
    __half* o = (z == 0) ? xo : (wo_ + (size_t)(z-1) * WSZ);
    float s = (z == 1) ? 0.08838834764831845f : 1.0f;
    float4 a = ((const float4*)in)[2*i];
    float4 b = ((const float4*)in)[2*i+1];
    uint4 r;
    r.x = packh(a.x*s, a.y*s); r.y = packh(a.z*s, a.w*s);
    r.z = packh(b.x*s, b.y*s); r.w = packh(b.z*s, b.w*s);
    ((uint4*)o)[i] = r;
}

// ============================================================
// Persistent plain-fp16 mma.sync GEMM: C = A @ B, BK=64,
// 3-stage cp.async ring across tiles, one sync per chunk,
// ordering: wait -> sync -> compute(ks 0-1) -> issue -> compute(ks 2-3).
// 2x4 warp grid, 2 CTAs/SM.
// fused: z=0 rope (Q, Wq pre-scaled), z=1 rope (K), z=2 plain (V); else fp32 out
// ============================================================
#define GBM 128
#define GBN 128
#define GBK 64
#define APAD 72
#define BPAD 136
#define SAB (GBM*APAD*2)            // 18432
#define SBB (GBK*BPAD*2)            // 17408
#define STAGE (SAB + SBB)           // 35840
#define GEMM_SMEM (3*STAGE)         // 107520 -> 2 CTAs/SM
#define CPT 32
#define TPZ (MROWS/GBM * DIM/GBN)   // 512

__global__ __launch_bounds__(256, 2) void gemm_fp16(
    const __half* __restrict__ A,
    const __half* __restrict__ B,
    __half* __restrict__ Qh, __half* __restrict__ Kh, __half* __restrict__ Vh,
    float* __restrict__ Cout,
    const float* __restrict__ fcos, const float* __restrict__ fsin,
    int fused, int ntiles)
{
    extern __shared__ char smraw[];
    const uint32_t sb = smem_u32(smraw);

    const int tid  = threadIdx.x;
    const int bid  = blockIdx.x;
    const int G    = gridDim.x;
    const int warp = tid >> 5, lane = tid & 31;
    const int wm = warp >> 2, wn = warp & 3;   // 2x4 grid, warp tile 64x32

    auto issue_chunk = [&](int myc) {
        int t = bid + (myc >> 5) * G;
        if (t >= ntiles) return;
        int z   = t / TPZ;
        int rem = t - z * TPZ;
        int row0 = (rem >> 4) * GBM;
        int col0 = (rem & 15) * GBN;
        const __half* bp = B + (size_t)z * WSZ;
        const uint32_t base = sb + (uint32_t)(myc % 3) * STAGE;
        const int k0 = (myc & (CPT-1)) * GBK;
        for (int idx = tid; idx < 1024; idx += 256) {
            int r = idx >> 3, o = (idx & 7) * 8;
            cp16(base + (uint32_t)(r * APAD + o) * 2,
                 A + (size_t)(row0 + r) * DIM + k0 + o);
        }
        for (int idx = tid; idx < 1024; idx += 256) {
            int r = idx >> 4, o = (idx & 15) * 8;
            cp16(base + SAB + (uint32_t)(r * BPAD + o) * 2,
                 bp + (size_t)(k0 + r) * DIM + col0 + o);
        }
    };

    issue_chunk(0);
    asm volatile("cp.async.commit_group;\n");
    issue_chunk(1);
    asm volatile("cp.async.commit_group;\n");

    const int arow  = (lane & 7) + ((lane >> 3) & 1) * 8;
    const int acol8 = (lane >> 4) * 8;
    const int brow8 = (lane & 7) + ((lane >> 3) & 1) * 8;
    const int bnc8  = (lane >> 4) * 8;

    int myc = 0;
    for (int t = bid; t < ntiles; t += G) {
        const int z   = t / TPZ;
        const int rem = t - z * TPZ;
        const int row0 = (rem >> 4) * GBM;
        const int col0 = (rem & 15) * GBN;
        const int mode = fused ? z : 3;

        float acc[4][4][4];
#pragma unroll
        for (int i = 0; i < 4; i++)
#pragma unroll
            for (int j = 0; j < 4; j++)
#pragma unroll
                for (int r = 0; r < 4; r++) acc[i][j][r] = 0.f;

        for (int i = 0; i < CPT; i++, myc++) {
            asm volatile("cp.async.wait_group 1;\n");  // chunk myc landed
            __syncthreads();                            // visibility + buffer (myc-1)%3 free

            const uint32_t base = sb + (uint32_t)(myc % 3) * STAGE;
            const uint32_t bA = base, bB = base + SAB;

#pragma unroll
            for (int ks = 0; ks < 4; ks++) {
                if (ks == 2) {                          // overlap LSU burst with tensor work
                    issue_chunk(myc + 2);
                    asm volatile("cp.async.commit_group;\n");
                }
                const int acol = ks * 16 + acol8;
                const int brow = ks * 16 + brow8;
                uint32_t bfr[4][2];
#pragma unroll
                for (int hh = 0; hh < 2; hh++) {
                    int nc = wn * 32 + hh * 16 + bnc8;
                    uint32_t t4[4];
                    ldsm4t(t4, bB + (uint32_t)(brow * BPAD + nc) * 2);
                    bfr[hh*2][0] = t4[0]; bfr[hh*2][1] = t4[1];
                    bfr[hh*2+1][0] = t4[2]; bfr[hh*2+1][1] = t4[3];
                }
                uint32_t af[4][4];
#pragma unroll
                for (int mt = 0; mt < 4; mt++)
                    ldsm4(af[mt], bA + (uint32_t)((wm*64 + mt*16 + arow) * APAD + acol) * 2);
#pragma unroll
                for (int mt = 0; mt < 4; mt++)
#pragma unroll
                    for (int nt = 0; nt < 4; nt++)
                        mma16816(acc[mt][nt], af[mt], bfr[nt]);
            }
        }

        // ---- fused epilogue ----
#pragma unroll
        for (int mt = 0; mt < 4; mt++) {
#pragma unroll
            for (int nt = 0; nt < 4; nt++) {
                int r = row0 + wm * 64 + mt * 16 + (lane >> 2);
                int c = col0 + wn * 32 + nt * 8 + (lane & 3) * 2;
                float a0 = acc[mt][nt][0], a1 = acc[mt][nt][1];
                float a2 = acc[mt][nt][2], a3 = acc[mt][nt][3];
                size_t o0 = (size_t)r * DIM + c, o1 = (size_t)(r + 8) * DIM + c;
                if (mode == 3) {
                    *(float2*)(Cout + o0) = make_float2(a0, a1);
                    *(float2*)(Cout + o1) = make_float2(a2, a3);
                } else if (mode == 2) {
                    *(uint32_t*)(Vh + o0) = packh(a0, a1);
                    *(uint32_t*)(Vh + o1) = packh(a2, a3);
                } else {
                    int i2 = (c & (HD - 1)) >> 1;
                    int s0 = r & (SEQ - 1), s1 = (r + 8) & (SEQ - 1);
                    float c0 = fcos[s0 * (HD/2) + i2], n0 = fsin[s0 * (HD/2) + i2];
                    float c1 = fcos[s1 * (HD/2) + i2], n1 = fsin[s1 * (HD/2) + i2];
                    float t0 = a0 * c0 - a1 * n0, t1 = a0 * n0 + a1 * c0;
                    float t2 = a2 * c1 - a3 * n1, t3 = a2 * n1 + a3 * c1;
                    __half* dst = (mode == 0) ? Qh : Kh;
                    *(uint32_t*)(dst + o0) = packh(t0, t1);
                    *(uint32_t*)(dst + o1) = packh(t2, t3);
                }
            }
        }
    }
}

// ============================================================
// Plain-fp16 causal flash attention, 64x64 tiles, 3 CTAs/SM.
// K(kt+1) prefetch issued right after the S-pass.
// ============================================================
#define AQ  64
#define APD 136
#define TILE_E (AQ*APD)
#define ATTN_SMEM (3*TILE_E*2)     // Q,K,V = 52224

__global__ __launch_bounds__(128, 3) void attn_tc_kernel(
    const __half* __restrict__ Qg, const __half* __restrict__ Kg,
    const __half* __restrict__ Vg, __half* __restrict__ Og)
{
    extern __shared__ __half sm[];
    __half* sQ = sm;
    __half* sK = sQ + TILE_E;
    __half* sV = sK + TILE_E;
    const uint32_t uQ = smem_u32(sQ);
    const uint32_t uK = smem_u32(sK);
    const uint32_t uV = smem_u32(sV);

    const int tid = threadIdx.x, warp = tid >> 5, lane = tid & 31;
    const int qt = (int)(gridDim.x - 1 - blockIdx.x);
    const int h = blockIdx.y, b = blockIdx.z;
    const int q0 = qt * AQ;
    const size_t rowbase = (size_t)b * SEQ;
    const size_t colh = (size_t)h * HD;

#define LOADTILE(dstu, src, r0) do {                                           \
    for (int c0_ = tid; c0_ < 1024; c0_ += 128) {                              \
        int r_ = c0_ >> 4, o_ = (c0_ & 15) * 8;                                \
        cp16((dstu) + (r_*APD + o_)*2,                                         \
             (src) + (rowbase + (r0) + r_)*DIM + colh + o_);                   \
    } } while (0)

    LOADTILE(uQ, Qg, q0);
    LOADTILE(uK, Kg, 0);
    asm volatile("cp.async.commit_group;\n");

    float o[16][4];
#pragma unroll
    for (int nt = 0; nt < 16; nt++)
#pragma unroll
        for (int r = 0; r < 4; r++) o[nt][r] = 0.f;
    float m0 = -INFINITY, m1 = -INFINITY, l0 = 0.f, l1 = 0.f;

    const int nkv = qt + 1;
    const int arow = (lane & 7) + ((lane >> 3) & 1) * 8;
    const int acol8 = (lane >> 4) * 8;
    const int bro8 = (lane & 7) + ((lane >> 4) << 3);
    const int bco8 = ((lane >> 3) & 1) * 8;
    const int vro8 = (lane & 7) + ((lane >> 3) & 1) * 8;
    const int vco8 = (lane >> 4) * 8;

    for (int kt = 0; kt < nkv; kt++) {
        // groups pending entering iter: ..., V(kt-1)?, K(kt). wait all -> K ready.
        asm volatile("cp.async.wait_group 0;\n");
        __syncthreads();

        LOADTILE(uV, Vg, kt*AQ);          // V(kt) -> group A
        asm volatile("cp.async.commit_group;\n");

        // ---- S = Q K^T ----
        float s[8][4];
#pragma unroll
        for (int t = 0; t < 8; t++)
#pragma unroll
            for (int r = 0; r < 4; r++) s[t][r] = 0.f;

#pragma unroll
        for (int ks = 0; ks < 8; ks++) {
            uint32_t q4[4];
            uint32_t aoff = ((warp*16 + arow)*APD + ks*16 + acol8)*2;
            ldsm4(q4, uQ + aoff);
#pragma unroll
            for (int bt = 0; bt < 4; bt++) {
                uint32_t k4[4];
                uint32_t boff = ((bt*16 + bro8)*APD + ks*16 + bco8)*2;
                ldsm4(k4, uK + boff);
                mma16816(s[2*bt],   q4, k4);
                mma16816(s[2*bt+1], q4, k4+2);
            }
        }

        // K smem reads done for this warp; barrier, then prefetch K(kt+1)
        __syncthreads();                   // ALL warps done reading K
        if (kt + 1 < nkv) {
            LOADTILE(uK, Kg, (kt+1)*AQ);   // K(kt+1) -> group B
        }
        asm volatile("cp.async.commit_group;\n");

        if (kt == qt) {
            int rl0 = warp*16 + (lane >> 2);
            int cb = (lane & 3) * 2;
#pragma unroll
            for (int t = 0; t < 8; t++) {
                int c0 = t*8 + cb, c1 = c0 + 1;
                if (c0 > rl0)     s[t][0] = -INFINITY;
                if (c1 > rl0)     s[t][1] = -INFINITY;
                if (c0 > rl0 + 8) s[t][2] = -INFINITY;
                if (c1 > rl0 + 8) s[t][3] = -INFINITY;
            }
        }

        float mt0 = -INFINITY, mt1 = -INFINITY;
#pragma unroll
        for (int t = 0; t < 8; t++) {
            mt0 = fmaxf(mt0, fmaxf(s[t][0], s[t][1]));
            mt1 = fmaxf(mt1, fmaxf(s[t][2], s[t][3]));
        }
        mt0 = fmaxf(mt0, __shfl_xor_sync(0xffffffffu, mt0, 1));
        mt0 = fmaxf(mt0, __shfl_xor_sync(0xffffffffu, mt0, 2));
        mt1 = fmaxf(mt1, __shfl_xor_sync(0xffffffffu, mt1, 1));
        mt1 = fmaxf(mt1, __shfl_xor_sync(0xffffffffu, mt1, 2));
        float mn0 = fmaxf(m0, mt0), mn1 = fmaxf(m1, mt1);
        float corr0 = __expf(m0 - mn0), corr1 = __expf(m1 - mn1);
        m0 = mn0; m1 = mn1;

        float p[8][4];
        float sum0 = 0.f, sum1 = 0.f;
#pragma unroll
        for (int t = 0; t < 8; t++) {
            p[t][0] = __expf(s[t][0] - mn0);
            p[t][1] = __expf(s[t][1] - mn0);
            p[t][2] = __expf(s[t][2] - mn1);
            p[t][3] = __expf(s[t][3] - mn1);
            sum0 += p[t][0] + p[t][1];
            sum1 += p[t][2] + p[t][3];
        }
        sum0 += __shfl_xor_sync(0xffffffffu, sum0, 1);
        sum0 += __shfl_xor_sync(0xffffffffu, sum0, 2);
        sum1 += __shfl_xor_sync(0xffffffffu, sum1, 1);
        sum1 += __shfl_xor_sync(0xffffffffu, sum1, 2);
        l0 = l0 * corr0 + sum0;
        l1 = l1 * corr1 + sum1;

        uint32_t ph[4][4];
#pragma unroll
        for (int c = 0; c < 4; c++) {
            ph[c][0] = packh(p[2*c][0],   p[2*c][1]);
            ph[c][1] = packh(p[2*c][2],   p[2*c][3]);
            ph[c][2] = packh(p[2*c+1][0], p[2*c+1][1]);
            ph[c][3] = packh(p[2*c+1][2], p[2*c+1][3]);
        }

#pragma unroll
        for (int nt = 0; nt < 16; nt++) {
            o[nt][0] *= corr0; o[nt][1] *= corr0;
            o[nt][2] *= corr1; o[nt][3] *= corr1;
        }

        // V(kt) ready (allow K(kt+1) still in flight)
        asm volatile("cp.async.wait_group 1;\n");
        __syncthreads();

        // ---- O += P V ----
#pragma unroll
        for (int c = 0; c < 4; c++) {
#pragma unroll
            for (int np = 0; np < 8; np++) {
                uint32_t v4[4];
                uint32_t voff = ((c*16 + vro8)*APD + np*16 + vco8)*2;
                ldsm4t(v4, uV + voff);
                mma16816(o[2*np],   ph[c], v4);
                mma16816(o[2*np+1], ph[c], v4+2);
            }
        }
        __syncthreads();   // V reads done before next iter's V overwrite
    }

    float inv0 = 1.f / l0, inv1 = 1.f / l1;
    size_t r0g = rowbase + q0 + warp*16 + (lane >> 2);
    size_t cg  = colh + (lane & 3)*2;
#pragma unroll
    for (int nt = 0; nt < 16; nt++) {
        size_t off0 = r0g*DIM + cg + nt*8;
        size_t off1 = (r0g+8)*DIM + cg + nt*8;
        *(uint32_t*)(Og + off0) = packh(o[nt][0]*inv0, o[nt][1]*inv0);
        *(uint32_t*)(Og + off1) = packh(o[nt][2]*inv1, o[nt][3]*inv1);
    }
}

// ============================================================
extern "C" void kernel_launch(void* const* d_in, const int* in_sizes, int n_in,
                              void* d_out, int out_size)
{
    const float* x   = (const float*)d_in[0];
    const float* wq  = (const float*)d_in[1];
    const float* wk  = (const float*)d_in[2];
    const float* wv  = (const float*)d_in[3];
    const float* wo  = (const float*)d_in[4];
    const float* fco = (const float*)d_in[5];
    const float* fsi = (const float*)d_in[6];
    float* out = (float*)d_out;

    __half *X, *W, *Qh, *Kh, *Vh, *Oh;
    cudaGetSymbolAddress((void**)&X,  g_X);
    cudaGetSymbolAddress((void**)&W,  g_W);
    cudaGetSymbolAddress((void**)&Qh, g_Qh);
    cudaGetSymbolAddress((void**)&Kh, g_Kh);
    cudaGetSymbolAddress((void**)&Vh, g_Vh);
    cudaGetSymbolAddress((void**)&Oh, g_Oh);

    cudaFuncSetAttribute(gemm_fp16,
        cudaFuncAttributeMaxDynamicSharedMemorySize, GEMM_SMEM);
    cudaFuncSetAttribute(attn_tc_kernel,
        cudaFuncAttributeMaxDynamicSharedMemorySize, ATTN_SMEM);

    const int n8x = MROWS * DIM / 8;    // 1,048,576
    const int n8w = DIM * DIM / 8;      //   524,288

    dim3 cgrid((n8x + 255)/256, 5);
    cvt5_kernel<<<cgrid, 256>>>(x, wq, wk, wv, wo, X, W, n8x, n8w);

    gemm_fp16<<<296, 256, GEMM_SMEM>>>(
        X, W, Qh, Kh, Vh,
        nullptr, fco, fsi, 1, 3*TPZ);

    dim3 agrid(SEQ / AQ, NH, BATCH);       // (32, 16, 2)
    attn_tc_kernel<<<agrid, 128, ATTN_SMEM>>>(Qh, Kh, Vh, Oh);

    gemm_fp16<<<296, 256, GEMM_SMEM>>>(
        Oh, W + 3*WSZ, nullptr, nullptr, nullptr,
        out, fco, fsi, 0, TPZ);
}